// round 12
// baseline (speedup 1.0000x reference)
#include <cuda_runtime.h>
#include <cuda_fp16.h>
#include <math.h>
#include <stdint.h>

#define L_SEQ   1024
#define BATCH   2
#define DMODEL  1024
#define DINNER  2048
#define NHEADS  32
#define HEADDIM 64
#define DSTATE  64
#define CONVDIM 2176
#define DINPROJ 4256
#define DINPROJ_PAD 4352
#define M_ROWS  2048   // BATCH * L_SEQ

// ===================== scratch (device globals) =============================
__device__ float g_zx[2][M_ROWS * DINPROJ];
__device__ float g_xbc[2][M_ROWS * CONVDIM];
__device__ float g_dt[2][M_ROWS * NHEADS];
__device__ float g_dA[2][M_ROWS * NHEADS];
__device__ float g_y[2][M_ROWS * DINNER];
__device__ float g_hbuf[M_ROWS * DMODEL];

__device__ __half g_xh[2][M_ROWS * DMODEL];          // dir0 = x, dir1 = flip(x)
__device__ __half g_wip_h[2][DINPROJ_PAD * DMODEL];  // in_proj weights (padded rows)
__device__ __half g_yh[2][M_ROWS * DINNER];          // gated/normed y
__device__ __half g_woh[2][DMODEL * DINNER];         // out_proj weights
__device__ __half g_cath[M_ROWS * DINNER];           // concat(fwd, flip(bwd)), fp16
__device__ __half g_wprh[DMODEL * DINNER];           // final proj weights

// ===================== small helpers ========================================
__device__ __forceinline__ uint32_t h2_as_u32(__half2 h) {
    uint32_t u;
    *(__half2*)&u = h;
    return u;
}
__device__ __forceinline__ uint32_t smem_u32(const void* p) {
    uint32_t a;
    asm("{ .reg .u64 t; cvta.to.shared.u64 t, %1; cvt.u32.u64 %0, t; }" : "=r"(a) : "l"(p));
    return a;
}
__device__ __forceinline__ void cp_async16(uint32_t s, const void* g) {
    asm volatile("cp.async.cg.shared.global [%0], [%1], 16;" :: "r"(s), "l"(g));
}
__device__ __forceinline__ void cp_async4(uint32_t s, const void* g) {
    asm volatile("cp.async.ca.shared.global [%0], [%1], 4;" :: "r"(s), "l"(g));
}
__device__ __forceinline__ void cp_commit() { asm volatile("cp.async.commit_group;" ::: "memory"); }
__device__ __forceinline__ void ldmatrix4(uint32_t& r0, uint32_t& r1, uint32_t& r2, uint32_t& r3, uint32_t a) {
    asm volatile("ldmatrix.sync.aligned.m8n8.x4.shared.b16 {%0,%1,%2,%3}, [%4];"
                 : "=r"(r0), "=r"(r1), "=r"(r2), "=r"(r3) : "r"(a));
}
__device__ __forceinline__ void mma16816(float* c, const uint32_t* a, const uint32_t* b) {
    asm volatile("mma.sync.aligned.m16n8k16.row.col.f32.f16.f16.f32 "
                 "{%0,%1,%2,%3}, {%4,%5,%6,%7}, {%8,%9}, {%0,%1,%2,%3};"
                 : "+f"(c[0]), "+f"(c[1]), "+f"(c[2]), "+f"(c[3])
                 : "r"(a[0]), "r"(a[1]), "r"(a[2]), "r"(a[3]), "r"(b[0]), "r"(b[1]));
}
__device__ __forceinline__ int fliprow(int r) { return ((r >> 10) << 10) + (1023 - (r & 1023)); }

// ===================== fp32 -> fp16 converts (8 elems/thread) ==============
__global__ void cvt_x_kernel(const float* __restrict__ x) {
    int idx = blockIdx.x * blockDim.x + threadIdx.x;     // 8-elem group
    if (idx >= M_ROWS * DMODEL / 8) return;
    int row = idx >> 7, c8 = idx & 127;
    const float4* s = (const float4*)(x) + idx * 2;
    float4 v0 = s[0], v1 = s[1];
    uint4 o;
    o.x = h2_as_u32(__floats2half2_rn(v0.x, v0.y));
    o.y = h2_as_u32(__floats2half2_rn(v0.z, v0.w));
    o.z = h2_as_u32(__floats2half2_rn(v1.x, v1.y));
    o.w = h2_as_u32(__floats2half2_rn(v1.z, v1.w));
    ((uint4*)g_xh[0])[idx] = o;
    ((uint4*)g_xh[1])[fliprow(row) * 128 + c8] = o;
}

__global__ void cvt_w_kernel(const float* __restrict__ w, __half* __restrict__ dst,
                             int n8src, int n8tot) {
    int idx = blockIdx.x * blockDim.x + threadIdx.x;
    if (idx >= n8tot) return;
    uint4 o;
    if (idx < n8src) {
        const float4* s = (const float4*)(w) + idx * 2;
        float4 v0 = s[0], v1 = s[1];
        o.x = h2_as_u32(__floats2half2_rn(v0.x, v0.y));
        o.y = h2_as_u32(__floats2half2_rn(v0.z, v0.w));
        o.z = h2_as_u32(__floats2half2_rn(v1.x, v1.y));
        o.w = h2_as_u32(__floats2half2_rn(v1.z, v1.w));
    } else {
        o = make_uint4(0, 0, 0, 0);
    }
    ((uint4*)dst)[idx] = o;
}

// ===================== HMMA fp16 GEMM (templated N tile) ====================
// C[M,N] = A[M,K] @ B[N,K]^T. CTA 128 x BNT, K-tile 64, 3-stage cp.async,
// 2 CTAs/SM. BNT=128 (verified 498us config) or BNT=64 (small-N grids).
#define KT 64
#define RS2 144                        // bytes per smem row (64 halves + 8 pad)
#define A_ST_BYTES (128 * RS2)         // 18432

template<int BNT>
__global__ __launch_bounds__(256, 2) void gemm_hmma(
    const __half* __restrict__ A0, size_t strideA,
    const __half* __restrict__ B0, size_t strideB,
    float* __restrict__ C0, size_t strideC,
    int K, int Nreal, int ldc, int emode)
{
    constexpr int B_ST = BNT * RS2;
    constexpr int STB = A_ST_BYTES + B_ST;
    constexpr int NI = BNT / 16;       // mma n-tiles per warp (8 or 4)
    constexpr int NJ = BNT / 32;       // ldmatrix b groups per warp (4 or 2)
    constexpr int BIT = BNT / 32;      // B load iterations (4 or 2)

    extern __shared__ char smem[];
    const uint32_t sb = smem_u32(smem);
    const int tid = threadIdx.x;
    const int lane = tid & 31;
    const int warp = tid >> 5;
    const int z = blockIdx.z;
    const __half* A = A0 + (size_t)z * strideA;
    const __half* B = B0 + (size_t)z * strideB;
    float* C = C0 + (size_t)z * strideC;
    const int bm = blockIdx.y * 128;
    const int bn = blockIdx.x * BNT;
    const int wm = (warp & 3) * 32;
    const int wn = (warp >> 2) * (BNT / 2);
    const int T = K / KT;

    auto load_stage = [&](int t, int s) {
        const uint32_t so = sb + (uint32_t)s * STB;
        const int k0 = t * KT;
#pragma unroll
        for (int it = 0; it < 4; it++) {
            int id = tid + (it << 8);
            int r = id >> 3, ck = id & 7;
            cp_async16(so + r * RS2 + ck * 16, A + (size_t)(bm + r) * K + k0 + ck * 8);
        }
#pragma unroll
        for (int it = 0; it < BIT; it++) {
            int id = tid + (it << 8);
            int r = id >> 3, ck = id & 7;
            cp_async16(so + A_ST_BYTES + r * RS2 + ck * 16, B + (size_t)(bn + r) * K + k0 + ck * 8);
        }
    };

    float acc[2][NI][4];
#pragma unroll
    for (int i = 0; i < 2; i++)
#pragma unroll
        for (int j = 0; j < NI; j++)
#pragma unroll
            for (int q = 0; q < 4; q++) acc[i][j][q] = 0.f;

    load_stage(0, 0); cp_commit();
    load_stage(1, 1); cp_commit();

    uint32_t a_off[2], b_off[NJ];
#pragma unroll
    for (int mi = 0; mi < 2; mi++)
        a_off[mi] = (wm + mi * 16 + (lane & 15)) * RS2 + ((lane >> 4) << 4);
#pragma unroll
    for (int nj = 0; nj < NJ; nj++)
        b_off[nj] = (uint32_t)(wn + nj * 16 + (lane & 7) + ((lane >> 4) << 3)) * RS2
                  + (((lane >> 3) & 1) << 4) + A_ST_BYTES;

    uint32_t fA[2][4];
    uint32_t fB[NI][2];
    int slot = 0;
#pragma unroll 1
    for (int t = 0; t < T; t++) {
        asm volatile("cp.async.wait_group 1;" ::: "memory");
        __syncthreads();
        if (t + 2 < T) {
            int ns = slot + 2; if (ns >= 3) ns -= 3;
            load_stage(t + 2, ns);
        }
        cp_commit();

        const uint32_t so = sb + (uint32_t)slot * STB;
#pragma unroll
        for (int k16 = 0; k16 < 4; k16++) {
#pragma unroll
            for (int mi = 0; mi < 2; mi++)
                ldmatrix4(fA[mi][0], fA[mi][1], fA[mi][2], fA[mi][3], so + a_off[mi] + k16 * 32);
#pragma unroll
            for (int nj = 0; nj < NJ; nj++) {
                uint32_t r0, r1, r2, r3;
                ldmatrix4(r0, r1, r2, r3, so + b_off[nj] + k16 * 32);
                fB[2 * nj][0] = r0;     fB[2 * nj][1] = r1;
                fB[2 * nj + 1][0] = r2; fB[2 * nj + 1][1] = r3;
            }
#pragma unroll
            for (int mi = 0; mi < 2; mi++)
#pragma unroll
                for (int ni = 0; ni < NI; ni++)
                    mma16816(acc[mi][ni], fA[mi], fB[ni]);
        }
        if (++slot == 3) slot = 0;
    }

    if (emode == 0) {
#pragma unroll
        for (int mi = 0; mi < 2; mi++) {
            int row = bm + wm + mi * 16 + (lane >> 2);
#pragma unroll
            for (int ni = 0; ni < NI; ni++) {
                int col = bn + wn + ni * 8 + ((lane & 3) << 1);
                if (col < Nreal) {
                    *(float2*)&C[(size_t)row * ldc + col] = make_float2(acc[mi][ni][0], acc[mi][ni][1]);
                    *(float2*)&C[(size_t)(row + 8) * ldc + col] = make_float2(acc[mi][ni][2], acc[mi][ni][3]);
                }
            }
        }
    } else {
        // fused concat: fp16 store with row-flip for z==1, col offset z*1024
#pragma unroll
        for (int mi = 0; mi < 2; mi++) {
            int r0 = bm + wm + mi * 16 + (lane >> 2);
            int r1 = r0 + 8;
            int cr0 = z ? fliprow(r0) : r0;
            int cr1 = z ? fliprow(r1) : r1;
#pragma unroll
            for (int ni = 0; ni < NI; ni++) {
                int col = bn + wn + ni * 8 + ((lane & 3) << 1) + (z << 10);
                __half2 h0 = __floats2half2_rn(acc[mi][ni][0], acc[mi][ni][1]);
                __half2 h1 = __floats2half2_rn(acc[mi][ni][2], acc[mi][ni][3]);
                *(__half2*)&g_cath[(size_t)cr0 * DINNER + col] = h0;
                *(__half2*)&g_cath[(size_t)cr1 * DINNER + col] = h1;
            }
        }
    }
}

#define G_SMEM128 (3 * (A_ST_BYTES + 128 * RS2))   // 110592
#define G_SMEM64  (3 * (A_ST_BYTES + 64 * RS2))    // 82944

// ===================== fp32 recompute of dt columns (verified) ==============
__global__ __launch_bounds__(256) void fix_dt_kernel(const float* __restrict__ x,
        const float* __restrict__ fw, const float* __restrict__ bw) {
    __shared__ float xs[DMODEL];
    int blk = blockIdx.x;
    int dir = blk >> 11;
    int row = blk & 2047;
    int srow = dir ? fliprow(row) : row;
    ((float4*)xs)[threadIdx.x] = ((const float4*)(x + (size_t)srow * DMODEL))[threadIdx.x];
    __syncthreads();
    int warp = threadIdx.x >> 5, lane = threadIdx.x & 31;
    const float* w = dir ? bw : fw;
#pragma unroll
    for (int hh = 0; hh < 4; hh++) {
        int h = warp * 4 + hh;
        const float4* wr = (const float4*)(w + (size_t)(DINNER + CONVDIM + h) * DMODEL);
        const float4* xv = (const float4*)xs;
        float s = 0.f;
#pragma unroll
        for (int j = 0; j < 8; j++) {
            int i = lane + (j << 5);
            float4 a = xv[i], b = wr[i];
            s = fmaf(a.x, b.x, s); s = fmaf(a.y, b.y, s);
            s = fmaf(a.z, b.z, s); s = fmaf(a.w, b.w, s);
        }
#pragma unroll
        for (int o = 16; o; o >>= 1) s += __shfl_xor_sync(0xffffffffu, s, o);
        if (lane == 0) g_zx[dir][(size_t)row * DINPROJ + (DINNER + CONVDIM) + h] = s;
    }
}

// ===================== dt / dA (verified) ===================================
__global__ void dt_kernel(const float* __restrict__ f_dtb, const float* __restrict__ f_alog,
                          const float* __restrict__ b_dtb, const float* __restrict__ b_alog) {
    int idx = blockIdx.x * blockDim.x + threadIdx.x;
    if (idx >= 2 * M_ROWS * NHEADS) return;
    int h = idx & 31;
    int r = idx >> 5;
    int dir = r >> 11;
    int row = r & 2047;
    const float* db = dir ? b_dtb : f_dtb;
    const float* al = dir ? b_alog : f_alog;
    float xr = g_zx[dir][(size_t)row * DINPROJ + (DINNER + CONVDIM) + h] + db[h];
    float dt = (xr > 20.f) ? xr : log1pf(expf(xr));
    float A = -expf(al[h]);
    g_dt[dir][row * NHEADS + h] = dt;
    g_dA[dir][row * NHEADS + h] = expf(dt * A);
}

// ===================== depthwise conv + silu (float4, verified) =============
__global__ void conv_silu(const float* __restrict__ fw, const float* __restrict__ fb,
                          const float* __restrict__ bw, const float* __restrict__ bb) {
    int idx = blockIdx.x * blockDim.x + threadIdx.x;   // float4 column groups
    if (idx >= 2 * M_ROWS * (CONVDIM / 4)) return;
    int c4 = idx % (CONVDIM / 4);
    int r = idx / (CONVDIM / 4);
    int dir = r >> 11;
    int row = r & 2047;
    int t = row & 1023;
    int c = c4 * 4;
    const float* w = dir ? bw : fw;
    const float* bias = dir ? bb : fb;
    const float* zx = g_zx[dir];
    float4 acc = *(const float4*)(bias + c);
#pragma unroll
    for (int j = 0; j < 4; j++) {
        int tj = t - 3 + j;
        if (tj >= 0) {
            float4 wv = *(const float4*)(w + j * CONVDIM + c);
            float4 xv = *(const float4*)(zx + (size_t)(row - 3 + j) * DINPROJ + DINNER + c);
            acc.x = fmaf(wv.x, xv.x, acc.x); acc.y = fmaf(wv.y, xv.y, acc.y);
            acc.z = fmaf(wv.z, xv.z, acc.z); acc.w = fmaf(wv.w, xv.w, acc.w);
        }
    }
    acc.x /= (1.f + expf(-acc.x)); acc.y /= (1.f + expf(-acc.y));
    acc.z /= (1.f + expf(-acc.z)); acc.w /= (1.f + expf(-acc.w));
    *(float4*)(&g_xbc[dir][(size_t)row * CONVDIM + c]) = acc;
}

// ===================== SSM scan (verified config) ===========================
#define SCH 8   // taus per chunk
__global__ __launch_bounds__(256) void scan_kernel() {
    __shared__ float sBC[2][SCH][160];   // 8 groups of 16 floats padded to 20
    __shared__ float sX[2][SCH][64];
    __shared__ float sS[2][SCH][2];      // [0]=dA [1]=dt

    int blk = blockIdx.x;
    int dir = blk >> 6;
    int b = (blk >> 5) & 1;
    int h = blk & 31;
    int t = threadIdx.x;
    int p = t >> 2;
    int s = t & 3;

    const float* xbc = g_xbc[dir] + (size_t)(b * L_SEQ) * CONVDIM;
    const float* dtb = g_dt[dir] + (size_t)(b * L_SEQ) * NHEADS + h;
    const float* dAb = g_dA[dir] + (size_t)(b * L_SEQ) * NHEADS + h;
    float* yout = g_y[dir] + (size_t)(b * L_SEQ) * DINNER + h * HEADDIM + p;

    auto prefetch = [&](int cc) {
        int bf = cc & 1;
#pragma unroll
        for (int i = 0; i < 2; i++) {
            int op = t + (i << 8);
            if (op < 384) {
                int tau = op / 48, j = op - tau * 48;
                int gtau = cc * SCH + tau;
                if (j < 32) {
                    int g = j >> 2;
                    cp_async16(smem_u32(&sBC[bf][tau][g * 20 + (j & 3) * 4]),
                               xbc + (size_t)gtau * CONVDIM + DINNER + j * 4);
                } else {
                    int jj = j - 32;
                    cp_async16(smem_u32(&sX[bf][tau][jj * 4]),
                               xbc + (size_t)gtau * CONVDIM + h * HEADDIM + jj * 4);
                }
            }
        }
        if (t < 16) {
            int tau = t >> 1;
            int gtau = cc * SCH + tau;
            const float* src = (t & 1) ? (dtb + gtau * NHEADS) : (dAb + gtau * NHEADS);
            cp_async4(smem_u32(&sS[bf][tau][t & 1]), src);
        }
    };

    float st[16];
#pragma unroll
    for (int i = 0; i < 16; i++) st[i] = 0.f;

    prefetch(0); cp_commit();
    prefetch(1); cp_commit();

#pragma unroll 1
    for (int cc = 0; cc < L_SEQ / SCH; cc++) {
        asm volatile("cp.async.wait_group 1;" ::: "memory");
        __syncthreads();
        int bf = cc & 1;
#pragma unroll
        for (int tl = 0; tl < SCH; tl++) {
            float dAv = sS[bf][tl][0];
            float dtv = sS[bf][tl][1];
            float xv  = sX[bf][tl][p];
            float coef = dtv * xv;
            const float4* Bp = (const float4*)&sBC[bf][tl][s * 20];
            const float4* Cp = (const float4*)&sBC[bf][tl][(4 + s) * 20];
            float4 B0 = Bp[0], B1 = Bp[1], B2 = Bp[2], B3 = Bp[3];
            float4 C0 = Cp[0], C1 = Cp[1], C2 = Cp[2], C3 = Cp[3];
            float acc = 0.f;
            st[ 0] = fmaf(st[ 0], dAv, coef * B0.x); acc = fmaf(st[ 0], C0.x, acc);
            st[ 1] = fmaf(st[ 1], dAv, coef * B0.y); acc = fmaf(st[ 1], C0.y, acc);
            st[ 2] = fmaf(st[ 2], dAv, coef * B0.z); acc = fmaf(st[ 2], C0.z, acc);
            st[ 3] = fmaf(st[ 3], dAv, coef * B0.w); acc = fmaf(st[ 3], C0.w, acc);
            st[ 4] = fmaf(st[ 4], dAv, coef * B1.x); acc = fmaf(st[ 4], C1.x, acc);
            st[ 5] = fmaf(st[ 5], dAv, coef * B1.y); acc = fmaf(st[ 5], C1.y, acc);
            st[ 6] = fmaf(st[ 6], dAv, coef * B1.z); acc = fmaf(st[ 6], C1.z, acc);
            st[ 7] = fmaf(st[ 7], dAv, coef * B1.w); acc = fmaf(st[ 7], C1.w, acc);
            st[ 8] = fmaf(st[ 8], dAv, coef * B2.x); acc = fmaf(st[ 8], C2.x, acc);
            st[ 9] = fmaf(st[ 9], dAv, coef * B2.y); acc = fmaf(st[ 9], C2.y, acc);
            st[10] = fmaf(st[10], dAv, coef * B2.z); acc = fmaf(st[10], C2.z, acc);
            st[11] = fmaf(st[11], dAv, coef * B2.w); acc = fmaf(st[11], C2.w, acc);
            st[12] = fmaf(st[12], dAv, coef * B3.x); acc = fmaf(st[12], C3.x, acc);
            st[13] = fmaf(st[13], dAv, coef * B3.y); acc = fmaf(st[13], C3.y, acc);
            st[14] = fmaf(st[14], dAv, coef * B3.z); acc = fmaf(st[14], C3.z, acc);
            st[15] = fmaf(st[15], dAv, coef * B3.w); acc = fmaf(st[15], C3.w, acc);
            acc += __shfl_xor_sync(0xffffffffu, acc, 1);
            acc += __shfl_xor_sync(0xffffffffu, acc, 2);
            if (s == 0) yout[(size_t)(cc * SCH + tl) * DINNER] = acc;
        }
        __syncthreads();
        if (cc + 2 < L_SEQ / SCH) prefetch(cc + 2);
        cp_commit();
    }
}

// ===================== gate + RMSNorm -> fp16 (float4) ======================
__global__ __launch_bounds__(256) void gate_rms(const float* __restrict__ fD, const float* __restrict__ frms,
                                                const float* __restrict__ bD, const float* __restrict__ brms) {
    int blk = blockIdx.x;
    int dir = blk >> 11;
    int row = blk & 2047;
    const float* Dp = dir ? bD : fD;
    const float* rw = dir ? brms : frms;
    const float4* zr = (const float4*)(g_zx[dir] + (size_t)row * DINPROJ);
    const float4* xr = (const float4*)(g_xbc[dir] + (size_t)row * CONVDIM);
    const float4* yr = (const float4*)(g_y[dir] + (size_t)row * DINNER);

    float vals[8];
    float ss = 0.f;
#pragma unroll
    for (int i = 0; i < 2; i++) {
        int g = threadIdx.x + (i << 8);
        float4 y4 = yr[g], z4 = zr[g], x4 = xr[g];
        float Dv = Dp[(g * 4) >> 6];
        float yv, zv;
        yv = fmaf(Dv, x4.x, y4.x); zv = z4.x; yv *= zv / (1.f + expf(-zv)); vals[i*4+0] = yv; ss = fmaf(yv, yv, ss);
        yv = fmaf(Dv, x4.y, y4.y); zv = z4.y; yv *= zv / (1.f + expf(-zv)); vals[i*4+1] = yv; ss = fmaf(yv, yv, ss);
        yv = fmaf(Dv, x4.z, y4.z); zv = z4.z; yv *= zv / (1.f + expf(-zv)); vals[i*4+2] = yv; ss = fmaf(yv, yv, ss);
        yv = fmaf(Dv, x4.w, y4.w); zv = z4.w; yv *= zv / (1.f + expf(-zv)); vals[i*4+3] = yv; ss = fmaf(yv, yv, ss);
    }
    __shared__ float red[8];
    __shared__ float s_scale;
#pragma unroll
    for (int o = 16; o; o >>= 1) ss += __shfl_xor_sync(0xffffffffu, ss, o);
    if ((threadIdx.x & 31) == 0) red[threadIdx.x >> 5] = ss;
    __syncthreads();
    if (threadIdx.x == 0) {
        float tot = 0.f;
#pragma unroll
        for (int i = 0; i < 8; i++) tot += red[i];
        s_scale = rsqrtf(tot / (float)DINNER + 1e-5f);
    }
    __syncthreads();
    float sc = s_scale;
#pragma unroll
    for (int i = 0; i < 2; i++) {
        int g = threadIdx.x + (i << 8);
        const float4 w4 = ((const float4*)rw)[g];
        float o0 = vals[i*4+0] * sc * w4.x;
        float o1 = vals[i*4+1] * sc * w4.y;
        float o2 = vals[i*4+2] * sc * w4.z;
        float o3 = vals[i*4+3] * sc * w4.w;
        uint2 st;
        st.x = h2_as_u32(__floats2half2_rn(o0, o1));
        st.y = h2_as_u32(__floats2half2_rn(o2, o3));
        ((uint2*)(g_yh[dir] + (size_t)row * DINNER))[g] = st;
    }
}

// ===================== residual + LayerNorm ================================
__global__ __launch_bounds__(256) void ln_kernel(const float* __restrict__ x,
        const float* __restrict__ pb, const float* __restrict__ lw,
        const float* __restrict__ lb, float* __restrict__ out) {
    int row = blockIdx.x;
    const float* hr = g_hbuf + (size_t)row * DMODEL;
    const float* xr = x + (size_t)row * DMODEL;
    float v[4];
    float sum = 0.f;
#pragma unroll
    for (int i = 0; i < 4; i++) {
        int c = threadIdx.x + (i << 8);
        v[i] = hr[c] + xr[c] + pb[c];
        sum += v[i];
    }
    __shared__ float red[8];
    __shared__ float s_mu, s_inv;
#pragma unroll
    for (int o = 16; o; o >>= 1) sum += __shfl_xor_sync(0xffffffffu, sum, o);
    if ((threadIdx.x & 31) == 0) red[threadIdx.x >> 5] = sum;
    __syncthreads();
    if (threadIdx.x == 0) {
        float tot = 0.f;
#pragma unroll
        for (int i = 0; i < 8; i++) tot += red[i];
        s_mu = tot / (float)DMODEL;
    }
    __syncthreads();
    float mu = s_mu;
    float vs = 0.f;
#pragma unroll
    for (int i = 0; i < 4; i++) { float d = v[i] - mu; vs = fmaf(d, d, vs); }
#pragma unroll
    for (int o = 16; o; o >>= 1) vs += __shfl_xor_sync(0xffffffffu, vs, o);
    if ((threadIdx.x & 31) == 0) red[threadIdx.x >> 5] = vs;
    __syncthreads();
    if (threadIdx.x == 0) {
        float tot = 0.f;
#pragma unroll
        for (int i = 0; i < 8; i++) tot += red[i];
        s_inv = rsqrtf(tot / (float)DMODEL + 1e-5f);
    }
    __syncthreads();
    float inv = s_inv;
#pragma unroll
    for (int i = 0; i < 4; i++) {
        int c = threadIdx.x + (i << 8);
        out[(size_t)row * DMODEL + c] = (v[i] - mu) * inv * lw[c] + lb[c];
    }
}

// ===================== host orchestration ===================================
extern "C" void kernel_launch(void* const* d_in, const int* in_sizes, int n_in,
                              void* d_out, int out_size) {
    const float* x            = (const float*)d_in[0];
    const float* f_in_proj_w  = (const float*)d_in[1];
    const float* f_conv_w     = (const float*)d_in[2];
    const float* f_conv_b     = (const float*)d_in[3];
    const float* f_dt_bias    = (const float*)d_in[4];
    const float* f_A_log      = (const float*)d_in[5];
    const float* f_D          = (const float*)d_in[6];
    const float* f_rms_w      = (const float*)d_in[7];
    const float* f_out_proj_w = (const float*)d_in[8];
    const float* b_in_proj_w  = (const float*)d_in[9];
    const float* b_conv_w     = (const float*)d_in[10];
    const float* b_conv_b     = (const float*)d_in[11];
    const float* b_dt_bias    = (const float*)d_in[12];
    const float* b_A_log      = (const float*)d_in[13];
    const float* b_D          = (const float*)d_in[14];
    const float* b_rms_w      = (const float*)d_in[15];
    const float* b_out_proj_w = (const float*)d_in[16];
    const float* proj_w       = (const float*)d_in[17];
    const float* proj_b       = (const float*)d_in[18];
    const float* ln_w         = (const float*)d_in[19];
    const float* ln_b         = (const float*)d_in[20];
    float* out = (float*)d_out;

    float *p_zx, *p_hbuf;
    __half *p_xh, *p_wip, *p_yh, *p_woh, *p_cath, *p_wprh;
    cudaGetSymbolAddress((void**)&p_zx, g_zx);
    cudaGetSymbolAddress((void**)&p_hbuf, g_hbuf);
    cudaGetSymbolAddress((void**)&p_xh, g_xh);
    cudaGetSymbolAddress((void**)&p_wip, g_wip_h);
    cudaGetSymbolAddress((void**)&p_yh, g_yh);
    cudaGetSymbolAddress((void**)&p_woh, g_woh);
    cudaGetSymbolAddress((void**)&p_cath, g_cath);
    cudaGetSymbolAddress((void**)&p_wprh, g_wprh);

    cudaFuncSetAttribute(gemm_hmma<128>, cudaFuncAttributeMaxDynamicSharedMemorySize, G_SMEM128);
    cudaFuncSetAttribute(gemm_hmma<64>,  cudaFuncAttributeMaxDynamicSharedMemorySize, G_SMEM64);

    const size_t XSZ  = (size_t)M_ROWS * DMODEL;
    const size_t WIPS = (size_t)DINPROJ_PAD * DMODEL;
    const size_t YSZ  = (size_t)M_ROWS * DINNER;
    const size_t WOS  = (size_t)DMODEL * DINNER;

    // 0) converts needed before in_proj
    cvt_x_kernel<<<(int)(XSZ / 8 / 256), 256>>>(x);
    cvt_w_kernel<<<(int)((WIPS / 8 + 255) / 256), 256>>>(f_in_proj_w, p_wip,        DINPROJ * DMODEL / 8, (int)(WIPS / 8));
    cvt_w_kernel<<<(int)((WIPS / 8 + 255) / 256), 256>>>(b_in_proj_w, p_wip + WIPS, DINPROJ * DMODEL / 8, (int)(WIPS / 8));
    cvt_w_kernel<<<(int)(WOS / 8 / 256), 256>>>(f_out_proj_w, p_woh,       (int)(WOS / 8), (int)(WOS / 8));
    cvt_w_kernel<<<(int)(WOS / 8 / 256), 256>>>(b_out_proj_w, p_woh + WOS, (int)(WOS / 8), (int)(WOS / 8));

    // 1) in_proj GEMMs merged over z: (2048,1024)@(4352,1024)^T -> g_zx
    {
        dim3 grid(DINPROJ_PAD / 128, M_ROWS / 128, 2);
        gemm_hmma<128><<<grid, 256, G_SMEM128>>>(p_xh, XSZ, p_wip, WIPS, p_zx, (size_t)M_ROWS * DINPROJ,
                                                 DMODEL, DINPROJ, DINPROJ, 0);
    }

    // deferred convert (needed only by step 6)
    cvt_w_kernel<<<(int)(WOS / 8 / 256), 256>>>(proj_w, p_wprh, (int)(WOS / 8), (int)(WOS / 8));

    // 1b) fp32 recompute of dt columns + dt/dA
    fix_dt_kernel<<<2 * M_ROWS, 256>>>(x, f_in_proj_w, b_in_proj_w);
    dt_kernel<<<(2 * M_ROWS * NHEADS + 255) / 256, 256>>>(f_dt_bias, f_A_log, b_dt_bias, b_A_log);

    // 2) conv + silu
    conv_silu<<<(2 * M_ROWS * (CONVDIM / 4) + 255) / 256, 256>>>(f_conv_w, f_conv_b, b_conv_w, b_conv_b);

    // 3) scan (smem staged)
    scan_kernel<<<128, 256>>>();

    // 4) gate + rmsnorm -> fp16
    gate_rms<<<2 * M_ROWS, 256>>>(f_D, f_rms_w, b_D, b_rms_w);

    // 5) out_proj GEMMs merged over z (BN=64 tiles: 512 CTAs), fused concat
    {
        dim3 grid(DMODEL / 64, M_ROWS / 128, 2);
        gemm_hmma<64><<<grid, 256, G_SMEM64>>>(p_yh, YSZ, p_woh, WOS, (float*)nullptr, 0,
                                               DINNER, DMODEL, DMODEL, 1);
    }

    // 6) final proj GEMM (BN=64 tiles: 256 CTAs): (2048,2048)@(1024,2048)^T
    {
        dim3 grid(DMODEL / 64, M_ROWS / 128, 1);
        gemm_hmma<64><<<grid, 256, G_SMEM64>>>(p_cath, 0, p_wprh, 0, p_hbuf, 0,
                                               DINNER, DMODEL, DMODEL, 0);
    }

    // 7) residual + LayerNorm
    ln_kernel<<<M_ROWS, 256>>>(x, proj_b, ln_w, ln_b, out);
}

// round 13
// speedup vs baseline: 1.0373x; 1.0373x over previous
#include <cuda_runtime.h>
#include <cuda_fp16.h>
#include <math.h>
#include <stdint.h>

#define L_SEQ   1024
#define BATCH   2
#define DMODEL  1024
#define DINNER  2048
#define NHEADS  32
#define HEADDIM 64
#define DSTATE  64
#define CONVDIM 2176
#define DINPROJ 4256
#define DINPROJ_PAD 4352
#define M_ROWS  2048   // BATCH * L_SEQ

// ===================== scratch (device globals) =============================
__device__ float g_zx[2][M_ROWS * DINPROJ];
__device__ float g_xbc[2][M_ROWS * CONVDIM];
__device__ float g_dt[2][M_ROWS * NHEADS];
__device__ float g_dA[2][M_ROWS * NHEADS];
__device__ float g_y[2][M_ROWS * DINNER];
__device__ float g_hbuf[M_ROWS * DMODEL];
__device__ float g_hbuf2[M_ROWS * DMODEL];           // split-K partial

__device__ __half g_xh[2][M_ROWS * DMODEL];          // dir0 = x, dir1 = flip(x)
__device__ __half g_wip_h[2][DINPROJ_PAD * DMODEL];  // in_proj weights (padded rows)
__device__ __half g_yh[2][M_ROWS * DINNER];          // gated/normed y
__device__ __half g_woh[2][DMODEL * DINNER];         // out_proj weights
__device__ __half g_cath[M_ROWS * DINNER];           // concat(fwd, flip(bwd)), fp16
__device__ __half g_wprh[DMODEL * DINNER];           // final proj weights

// ===================== small helpers ========================================
__device__ __forceinline__ uint32_t h2_as_u32(__half2 h) {
    uint32_t u;
    *(__half2*)&u = h;
    return u;
}
__device__ __forceinline__ uint32_t smem_u32(const void* p) {
    uint32_t a;
    asm("{ .reg .u64 t; cvta.to.shared.u64 t, %1; cvt.u32.u64 %0, t; }" : "=r"(a) : "l"(p));
    return a;
}
__device__ __forceinline__ void cp_async16(uint32_t s, const void* g) {
    asm volatile("cp.async.cg.shared.global [%0], [%1], 16;" :: "r"(s), "l"(g));
}
__device__ __forceinline__ void cp_async4(uint32_t s, const void* g) {
    asm volatile("cp.async.ca.shared.global [%0], [%1], 4;" :: "r"(s), "l"(g));
}
__device__ __forceinline__ void cp_commit() { asm volatile("cp.async.commit_group;" ::: "memory"); }
__device__ __forceinline__ void ldmatrix4(uint32_t& r0, uint32_t& r1, uint32_t& r2, uint32_t& r3, uint32_t a) {
    asm volatile("ldmatrix.sync.aligned.m8n8.x4.shared.b16 {%0,%1,%2,%3}, [%4];"
                 : "=r"(r0), "=r"(r1), "=r"(r2), "=r"(r3) : "r"(a));
}
__device__ __forceinline__ void mma16816(float* c, const uint32_t* a, const uint32_t* b) {
    asm volatile("mma.sync.aligned.m16n8k16.row.col.f32.f16.f16.f32 "
                 "{%0,%1,%2,%3}, {%4,%5,%6,%7}, {%8,%9}, {%0,%1,%2,%3};"
                 : "+f"(c[0]), "+f"(c[1]), "+f"(c[2]), "+f"(c[3])
                 : "r"(a[0]), "r"(a[1]), "r"(a[2]), "r"(a[3]), "r"(b[0]), "r"(b[1]));
}
__device__ __forceinline__ int fliprow(int r) { return ((r >> 10) << 10) + (1023 - (r & 1023)); }

// ===================== fp32 -> fp16 converts (8 elems/thread) ==============
__global__ void cvt_x_kernel(const float* __restrict__ x) {
    int idx = blockIdx.x * blockDim.x + threadIdx.x;     // 8-elem group
    if (idx >= M_ROWS * DMODEL / 8) return;
    int row = idx >> 7, c8 = idx & 127;
    const float4* s = (const float4*)(x) + idx * 2;
    float4 v0 = s[0], v1 = s[1];
    uint4 o;
    o.x = h2_as_u32(__floats2half2_rn(v0.x, v0.y));
    o.y = h2_as_u32(__floats2half2_rn(v0.z, v0.w));
    o.z = h2_as_u32(__floats2half2_rn(v1.x, v1.y));
    o.w = h2_as_u32(__floats2half2_rn(v1.z, v1.w));
    ((uint4*)g_xh[0])[idx] = o;
    ((uint4*)g_xh[1])[fliprow(row) * 128 + c8] = o;
}

__global__ void cvt_w_kernel(const float* __restrict__ w, __half* __restrict__ dst,
                             int n8src, int n8tot) {
    int idx = blockIdx.x * blockDim.x + threadIdx.x;
    if (idx >= n8tot) return;
    uint4 o;
    if (idx < n8src) {
        const float4* s = (const float4*)(w) + idx * 2;
        float4 v0 = s[0], v1 = s[1];
        o.x = h2_as_u32(__floats2half2_rn(v0.x, v0.y));
        o.y = h2_as_u32(__floats2half2_rn(v0.z, v0.w));
        o.z = h2_as_u32(__floats2half2_rn(v1.x, v1.y));
        o.w = h2_as_u32(__floats2half2_rn(v1.z, v1.w));
    } else {
        o = make_uint4(0, 0, 0, 0);
    }
    ((uint4*)dst)[idx] = o;
}

// ===================== HMMA fp16 GEMM (verified 498us config) ===============
// C[M,N] = A[M,K] @ B[N,K]^T. CTA 128x128, K-tile 64, 3-stage cp.async,
// 2 CTAs/SM. blockIdx.z selects (A,B,C) offset triple -> also used for split-K.
#define KT 64
#define RS2 144                        // bytes per smem row (64 halves + 8 pad)
#define A_ST_BYTES (128 * RS2)         // 18432
#define ST_BYTES   (2 * A_ST_BYTES)    // 36864 per stage
#define NSTAGE 3
#define G_SMEM (NSTAGE * ST_BYTES)     // 110592 -> 2 CTAs/SM

struct Frag { uint32_t A[2][4]; uint32_t B[8][2]; };

__device__ __forceinline__ void load_frags(uint32_t so, int k16,
        const uint32_t* a_off, const uint32_t* b_off, Frag& f) {
#pragma unroll
    for (int mi = 0; mi < 2; mi++)
        ldmatrix4(f.A[mi][0], f.A[mi][1], f.A[mi][2], f.A[mi][3], so + a_off[mi] + k16 * 32);
#pragma unroll
    for (int nj = 0; nj < 4; nj++) {
        uint32_t r0, r1, r2, r3;
        ldmatrix4(r0, r1, r2, r3, so + b_off[nj] + k16 * 32);
        f.B[2 * nj][0] = r0;     f.B[2 * nj][1] = r1;
        f.B[2 * nj + 1][0] = r2; f.B[2 * nj + 1][1] = r3;
    }
}

// ldA/ldB = row strides of A/B (may exceed K when split-K slices a wider matrix)
__global__ __launch_bounds__(256, 2) void gemm_hmma(
    const __half* __restrict__ A0, size_t strideA,
    const __half* __restrict__ B0, size_t strideB,
    float* __restrict__ C0, size_t strideC,
    int K, int ldA, int ldB, int Nreal, int ldc, int emode)
{
    extern __shared__ char smem[];
    const uint32_t sb = smem_u32(smem);
    const int tid = threadIdx.x;
    const int lane = tid & 31;
    const int warp = tid >> 5;
    const int z = blockIdx.z;
    const __half* A = A0 + (size_t)z * strideA;
    const __half* B = B0 + (size_t)z * strideB;
    float* C = C0 + (size_t)z * strideC;
    const int bm = blockIdx.y * 128;
    const int bn = blockIdx.x * 128;
    const int wm = (warp & 3) * 32;
    const int wn = (warp >> 2) * 64;
    const int T = K / KT;

    auto load_stage = [&](int t, int s) {
        const uint32_t so = sb + (uint32_t)s * ST_BYTES;
        const int k0 = t * KT;
#pragma unroll
        for (int it = 0; it < 4; it++) {
            int id = tid + (it << 8);
            int r = id >> 3, ck = id & 7;
            uint32_t sm = so + r * RS2 + ck * 16;
            cp_async16(sm, A + (size_t)(bm + r) * ldA + k0 + ck * 8);
            cp_async16(sm + A_ST_BYTES, B + (size_t)(bn + r) * ldB + k0 + ck * 8);
        }
    };

    float acc[2][8][4];
#pragma unroll
    for (int i = 0; i < 2; i++)
#pragma unroll
        for (int j = 0; j < 8; j++)
#pragma unroll
            for (int q = 0; q < 4; q++) acc[i][j][q] = 0.f;

    load_stage(0, 0); cp_commit();
    load_stage(1, 1); cp_commit();

    uint32_t a_off[2], b_off[4];
#pragma unroll
    for (int mi = 0; mi < 2; mi++)
        a_off[mi] = (wm + mi * 16 + (lane & 15)) * RS2 + ((lane >> 4) << 4);
#pragma unroll
    for (int nj = 0; nj < 4; nj++)
        b_off[nj] = (uint32_t)(wn + nj * 16 + (lane & 7) + ((lane >> 4) << 3)) * RS2
                  + (((lane >> 3) & 1) << 4) + A_ST_BYTES;

    Frag f;
    int slot = 0;
#pragma unroll 1
    for (int t = 0; t < T; t++) {
        asm volatile("cp.async.wait_group 1;" ::: "memory");
        __syncthreads();
        if (t + 2 < T) {
            int ns = slot + 2; if (ns >= 3) ns -= 3;
            load_stage(t + 2, ns);
        }
        cp_commit();

        const uint32_t so = sb + (uint32_t)slot * ST_BYTES;
#pragma unroll
        for (int k16 = 0; k16 < 4; k16++) {
            load_frags(so, k16, a_off, b_off, f);
#pragma unroll
            for (int mi = 0; mi < 2; mi++)
#pragma unroll
                for (int ni = 0; ni < 8; ni++)
                    mma16816(acc[mi][ni], f.A[mi], f.B[ni]);
        }
        if (++slot == 3) slot = 0;
    }

    if (emode == 0) {
#pragma unroll
        for (int mi = 0; mi < 2; mi++) {
            int row = bm + wm + mi * 16 + (lane >> 2);
#pragma unroll
            for (int ni = 0; ni < 8; ni++) {
                int col = bn + wn + ni * 8 + ((lane & 3) << 1);
                if (col < Nreal) {
                    *(float2*)&C[(size_t)row * ldc + col] = make_float2(acc[mi][ni][0], acc[mi][ni][1]);
                    *(float2*)&C[(size_t)(row + 8) * ldc + col] = make_float2(acc[mi][ni][2], acc[mi][ni][3]);
                }
            }
        }
    } else {
        // fused concat: fp16 store with row-flip for z==1, col offset z*1024
#pragma unroll
        for (int mi = 0; mi < 2; mi++) {
            int r0 = bm + wm + mi * 16 + (lane >> 2);
            int r1 = r0 + 8;
            int cr0 = z ? fliprow(r0) : r0;
            int cr1 = z ? fliprow(r1) : r1;
#pragma unroll
            for (int ni = 0; ni < 8; ni++) {
                int col = bn + wn + ni * 8 + ((lane & 3) << 1) + (z << 10);
                __half2 h0 = __floats2half2_rn(acc[mi][ni][0], acc[mi][ni][1]);
                __half2 h1 = __floats2half2_rn(acc[mi][ni][2], acc[mi][ni][3]);
                *(__half2*)&g_cath[(size_t)cr0 * DINNER + col] = h0;
                *(__half2*)&g_cath[(size_t)cr1 * DINNER + col] = h1;
            }
        }
    }
}

// ===================== fp32 recompute of dt columns (verified) ==============
__global__ __launch_bounds__(256) void fix_dt_kernel(const float* __restrict__ x,
        const float* __restrict__ fw, const float* __restrict__ bw) {
    __shared__ float xs[DMODEL];
    int blk = blockIdx.x;
    int dir = blk >> 11;
    int row = blk & 2047;
    int srow = dir ? fliprow(row) : row;
    ((float4*)xs)[threadIdx.x] = ((const float4*)(x + (size_t)srow * DMODEL))[threadIdx.x];
    __syncthreads();
    int warp = threadIdx.x >> 5, lane = threadIdx.x & 31;
    const float* w = dir ? bw : fw;
#pragma unroll
    for (int hh = 0; hh < 4; hh++) {
        int h = warp * 4 + hh;
        const float4* wr = (const float4*)(w + (size_t)(DINNER + CONVDIM + h) * DMODEL);
        const float4* xv = (const float4*)xs;
        float s = 0.f;
#pragma unroll
        for (int j = 0; j < 8; j++) {
            int i = lane + (j << 5);
            float4 a = xv[i], b = wr[i];
            s = fmaf(a.x, b.x, s); s = fmaf(a.y, b.y, s);
            s = fmaf(a.z, b.z, s); s = fmaf(a.w, b.w, s);
        }
#pragma unroll
        for (int o = 16; o; o >>= 1) s += __shfl_xor_sync(0xffffffffu, s, o);
        if (lane == 0) g_zx[dir][(size_t)row * DINPROJ + (DINNER + CONVDIM) + h] = s;
    }
}

// ===================== dt / dA (verified) ===================================
__global__ void dt_kernel(const float* __restrict__ f_dtb, const float* __restrict__ f_alog,
                          const float* __restrict__ b_dtb, const float* __restrict__ b_alog) {
    int idx = blockIdx.x * blockDim.x + threadIdx.x;
    if (idx >= 2 * M_ROWS * NHEADS) return;
    int h = idx & 31;
    int r = idx >> 5;
    int dir = r >> 11;
    int row = r & 2047;
    const float* db = dir ? b_dtb : f_dtb;
    const float* al = dir ? b_alog : f_alog;
    float xr = g_zx[dir][(size_t)row * DINPROJ + (DINNER + CONVDIM) + h] + db[h];
    float dt = (xr > 20.f) ? xr : log1pf(expf(xr));
    float A = -expf(al[h]);
    g_dt[dir][row * NHEADS + h] = dt;
    g_dA[dir][row * NHEADS + h] = expf(dt * A);
}

// ===================== depthwise conv + silu (float4, verified) =============
__global__ void conv_silu(const float* __restrict__ fw, const float* __restrict__ fb,
                          const float* __restrict__ bw, const float* __restrict__ bb) {
    int idx = blockIdx.x * blockDim.x + threadIdx.x;   // float4 column groups
    if (idx >= 2 * M_ROWS * (CONVDIM / 4)) return;
    int c4 = idx % (CONVDIM / 4);
    int r = idx / (CONVDIM / 4);
    int dir = r >> 11;
    int row = r & 2047;
    int t = row & 1023;
    int c = c4 * 4;
    const float* w = dir ? bw : fw;
    const float* bias = dir ? bb : fb;
    const float* zx = g_zx[dir];
    float4 acc = *(const float4*)(bias + c);
#pragma unroll
    for (int j = 0; j < 4; j++) {
        int tj = t - 3 + j;
        if (tj >= 0) {
            float4 wv = *(const float4*)(w + j * CONVDIM + c);
            float4 xv = *(const float4*)(zx + (size_t)(row - 3 + j) * DINPROJ + DINNER + c);
            acc.x = fmaf(wv.x, xv.x, acc.x); acc.y = fmaf(wv.y, xv.y, acc.y);
            acc.z = fmaf(wv.z, xv.z, acc.z); acc.w = fmaf(wv.w, xv.w, acc.w);
        }
    }
    acc.x /= (1.f + expf(-acc.x)); acc.y /= (1.f + expf(-acc.y));
    acc.z /= (1.f + expf(-acc.z)); acc.w /= (1.f + expf(-acc.w));
    *(float4*)(&g_xbc[dir][(size_t)row * CONVDIM + c]) = acc;
}

// ===================== SSM scan (verified config) ===========================
#define SCH 8   // taus per chunk
__global__ __launch_bounds__(256) void scan_kernel() {
    __shared__ float sBC[2][SCH][160];   // 8 groups of 16 floats padded to 20
    __shared__ float sX[2][SCH][64];
    __shared__ float sS[2][SCH][2];      // [0]=dA [1]=dt

    int blk = blockIdx.x;
    int dir = blk >> 6;
    int b = (blk >> 5) & 1;
    int h = blk & 31;
    int t = threadIdx.x;
    int p = t >> 2;
    int s = t & 3;

    const float* xbc = g_xbc[dir] + (size_t)(b * L_SEQ) * CONVDIM;
    const float* dtb = g_dt[dir] + (size_t)(b * L_SEQ) * NHEADS + h;
    const float* dAb = g_dA[dir] + (size_t)(b * L_SEQ) * NHEADS + h;
    float* yout = g_y[dir] + (size_t)(b * L_SEQ) * DINNER + h * HEADDIM + p;

    auto prefetch = [&](int cc) {
        int bf = cc & 1;
#pragma unroll
        for (int i = 0; i < 2; i++) {
            int op = t + (i << 8);
            if (op < 384) {
                int tau = op / 48, j = op - tau * 48;
                int gtau = cc * SCH + tau;
                if (j < 32) {
                    int g = j >> 2;
                    cp_async16(smem_u32(&sBC[bf][tau][g * 20 + (j & 3) * 4]),
                               xbc + (size_t)gtau * CONVDIM + DINNER + j * 4);
                } else {
                    int jj = j - 32;
                    cp_async16(smem_u32(&sX[bf][tau][jj * 4]),
                               xbc + (size_t)gtau * CONVDIM + h * HEADDIM + jj * 4);
                }
            }
        }
        if (t < 16) {
            int tau = t >> 1;
            int gtau = cc * SCH + tau;
            const float* src = (t & 1) ? (dtb + gtau * NHEADS) : (dAb + gtau * NHEADS);
            cp_async4(smem_u32(&sS[bf][tau][t & 1]), src);
        }
    };

    float st[16];
#pragma unroll
    for (int i = 0; i < 16; i++) st[i] = 0.f;

    prefetch(0); cp_commit();
    prefetch(1); cp_commit();

#pragma unroll 1
    for (int cc = 0; cc < L_SEQ / SCH; cc++) {
        asm volatile("cp.async.wait_group 1;" ::: "memory");
        __syncthreads();
        int bf = cc & 1;
#pragma unroll
        for (int tl = 0; tl < SCH; tl++) {
            float dAv = sS[bf][tl][0];
            float dtv = sS[bf][tl][1];
            float xv  = sX[bf][tl][p];
            float coef = dtv * xv;
            const float4* Bp = (const float4*)&sBC[bf][tl][s * 20];
            const float4* Cp = (const float4*)&sBC[bf][tl][(4 + s) * 20];
            float4 B0 = Bp[0], B1 = Bp[1], B2 = Bp[2], B3 = Bp[3];
            float4 C0 = Cp[0], C1 = Cp[1], C2 = Cp[2], C3 = Cp[3];
            float acc = 0.f;
            st[ 0] = fmaf(st[ 0], dAv, coef * B0.x); acc = fmaf(st[ 0], C0.x, acc);
            st[ 1] = fmaf(st[ 1], dAv, coef * B0.y); acc = fmaf(st[ 1], C0.y, acc);
            st[ 2] = fmaf(st[ 2], dAv, coef * B0.z); acc = fmaf(st[ 2], C0.z, acc);
            st[ 3] = fmaf(st[ 3], dAv, coef * B0.w); acc = fmaf(st[ 3], C0.w, acc);
            st[ 4] = fmaf(st[ 4], dAv, coef * B1.x); acc = fmaf(st[ 4], C1.x, acc);
            st[ 5] = fmaf(st[ 5], dAv, coef * B1.y); acc = fmaf(st[ 5], C1.y, acc);
            st[ 6] = fmaf(st[ 6], dAv, coef * B1.z); acc = fmaf(st[ 6], C1.z, acc);
            st[ 7] = fmaf(st[ 7], dAv, coef * B1.w); acc = fmaf(st[ 7], C1.w, acc);
            st[ 8] = fmaf(st[ 8], dAv, coef * B2.x); acc = fmaf(st[ 8], C2.x, acc);
            st[ 9] = fmaf(st[ 9], dAv, coef * B2.y); acc = fmaf(st[ 9], C2.y, acc);
            st[10] = fmaf(st[10], dAv, coef * B2.z); acc = fmaf(st[10], C2.z, acc);
            st[11] = fmaf(st[11], dAv, coef * B2.w); acc = fmaf(st[11], C2.w, acc);
            st[12] = fmaf(st[12], dAv, coef * B3.x); acc = fmaf(st[12], C3.x, acc);
            st[13] = fmaf(st[13], dAv, coef * B3.y); acc = fmaf(st[13], C3.y, acc);
            st[14] = fmaf(st[14], dAv, coef * B3.z); acc = fmaf(st[14], C3.z, acc);
            st[15] = fmaf(st[15], dAv, coef * B3.w); acc = fmaf(st[15], C3.w, acc);
            acc += __shfl_xor_sync(0xffffffffu, acc, 1);
            acc += __shfl_xor_sync(0xffffffffu, acc, 2);
            if (s == 0) yout[(size_t)(cc * SCH + tl) * DINNER] = acc;
        }
        __syncthreads();
        if (cc + 2 < L_SEQ / SCH) prefetch(cc + 2);
        cp_commit();
    }
}

// ===================== gate + RMSNorm -> fp16 (float4) ======================
__global__ __launch_bounds__(256) void gate_rms(const float* __restrict__ fD, const float* __restrict__ frms,
                                                const float* __restrict__ bD, const float* __restrict__ brms) {
    int blk = blockIdx.x;
    int dir = blk >> 11;
    int row = blk & 2047;
    const float* Dp = dir ? bD : fD;
    const float* rw = dir ? brms : frms;
    const float4* zr = (const float4*)(g_zx[dir] + (size_t)row * DINPROJ);
    const float4* xr = (const float4*)(g_xbc[dir] + (size_t)row * CONVDIM);
    const float4* yr = (const float4*)(g_y[dir] + (size_t)row * DINNER);

    float vals[8];
    float ss = 0.f;
#pragma unroll
    for (int i = 0; i < 2; i++) {
        int g = threadIdx.x + (i << 8);
        float4 y4 = yr[g], z4 = zr[g], x4 = xr[g];
        float Dv = Dp[(g * 4) >> 6];
        float yv, zv;
        yv = fmaf(Dv, x4.x, y4.x); zv = z4.x; yv *= zv / (1.f + expf(-zv)); vals[i*4+0] = yv; ss = fmaf(yv, yv, ss);
        yv = fmaf(Dv, x4.y, y4.y); zv = z4.y; yv *= zv / (1.f + expf(-zv)); vals[i*4+1] = yv; ss = fmaf(yv, yv, ss);
        yv = fmaf(Dv, x4.z, y4.z); zv = z4.z; yv *= zv / (1.f + expf(-zv)); vals[i*4+2] = yv; ss = fmaf(yv, yv, ss);
        yv = fmaf(Dv, x4.w, y4.w); zv = z4.w; yv *= zv / (1.f + expf(-zv)); vals[i*4+3] = yv; ss = fmaf(yv, yv, ss);
    }
    __shared__ float red[8];
    __shared__ float s_scale;
#pragma unroll
    for (int o = 16; o; o >>= 1) ss += __shfl_xor_sync(0xffffffffu, ss, o);
    if ((threadIdx.x & 31) == 0) red[threadIdx.x >> 5] = ss;
    __syncthreads();
    if (threadIdx.x == 0) {
        float tot = 0.f;
#pragma unroll
        for (int i = 0; i < 8; i++) tot += red[i];
        s_scale = rsqrtf(tot / (float)DINNER + 1e-5f);
    }
    __syncthreads();
    float sc = s_scale;
#pragma unroll
    for (int i = 0; i < 2; i++) {
        int g = threadIdx.x + (i << 8);
        const float4 w4 = ((const float4*)rw)[g];
        float o0 = vals[i*4+0] * sc * w4.x;
        float o1 = vals[i*4+1] * sc * w4.y;
        float o2 = vals[i*4+2] * sc * w4.z;
        float o3 = vals[i*4+3] * sc * w4.w;
        uint2 st;
        st.x = h2_as_u32(__floats2half2_rn(o0, o1));
        st.y = h2_as_u32(__floats2half2_rn(o2, o3));
        ((uint2*)(g_yh[dir] + (size_t)row * DINNER))[g] = st;
    }
}

// ===================== residual + LayerNorm (adds split-K partials) =========
__global__ __launch_bounds__(256) void ln_kernel(const float* __restrict__ x,
        const float* __restrict__ pb, const float* __restrict__ lw,
        const float* __restrict__ lb, float* __restrict__ out) {
    int row = blockIdx.x;
    const float* hr  = g_hbuf  + (size_t)row * DMODEL;
    const float* hr2 = g_hbuf2 + (size_t)row * DMODEL;
    const float* xr = x + (size_t)row * DMODEL;
    float v[4];
    float sum = 0.f;
#pragma unroll
    for (int i = 0; i < 4; i++) {
        int c = threadIdx.x + (i << 8);
        v[i] = (hr[c] + hr2[c]) + xr[c] + pb[c];
        sum += v[i];
    }
    __shared__ float red[8];
    __shared__ float s_mu, s_inv;
#pragma unroll
    for (int o = 16; o; o >>= 1) sum += __shfl_xor_sync(0xffffffffu, sum, o);
    if ((threadIdx.x & 31) == 0) red[threadIdx.x >> 5] = sum;
    __syncthreads();
    if (threadIdx.x == 0) {
        float tot = 0.f;
#pragma unroll
        for (int i = 0; i < 8; i++) tot += red[i];
        s_mu = tot / (float)DMODEL;
    }
    __syncthreads();
    float mu = s_mu;
    float vs = 0.f;
#pragma unroll
    for (int i = 0; i < 4; i++) { float d = v[i] - mu; vs = fmaf(d, d, vs); }
#pragma unroll
    for (int o = 16; o; o >>= 1) vs += __shfl_xor_sync(0xffffffffu, vs, o);
    if ((threadIdx.x & 31) == 0) red[threadIdx.x >> 5] = vs;
    __syncthreads();
    if (threadIdx.x == 0) {
        float tot = 0.f;
#pragma unroll
        for (int i = 0; i < 8; i++) tot += red[i];
        s_inv = rsqrtf(tot / (float)DMODEL + 1e-5f);
    }
    __syncthreads();
    float inv = s_inv;
#pragma unroll
    for (int i = 0; i < 4; i++) {
        int c = threadIdx.x + (i << 8);
        out[(size_t)row * DMODEL + c] = (v[i] - mu) * inv * lw[c] + lb[c];
    }
}

// ===================== host orchestration ===================================
extern "C" void kernel_launch(void* const* d_in, const int* in_sizes, int n_in,
                              void* d_out, int out_size) {
    const float* x            = (const float*)d_in[0];
    const float* f_in_proj_w  = (const float*)d_in[1];
    const float* f_conv_w     = (const float*)d_in[2];
    const float* f_conv_b     = (const float*)d_in[3];
    const float* f_dt_bias    = (const float*)d_in[4];
    const float* f_A_log      = (const float*)d_in[5];
    const float* f_D          = (const float*)d_in[6];
    const float* f_rms_w      = (const float*)d_in[7];
    const float* f_out_proj_w = (const float*)d_in[8];
    const float* b_in_proj_w  = (const float*)d_in[9];
    const float* b_conv_w     = (const float*)d_in[10];
    const float* b_conv_b     = (const float*)d_in[11];
    const float* b_dt_bias    = (const float*)d_in[12];
    const float* b_A_log      = (const float*)d_in[13];
    const float* b_D          = (const float*)d_in[14];
    const float* b_rms_w      = (const float*)d_in[15];
    const float* b_out_proj_w = (const float*)d_in[16];
    const float* proj_w       = (const float*)d_in[17];
    const float* proj_b       = (const float*)d_in[18];
    const float* ln_w         = (const float*)d_in[19];
    const float* ln_b         = (const float*)d_in[20];
    float* out = (float*)d_out;

    float *p_zx, *p_hbuf, *p_hbuf2;
    __half *p_xh, *p_wip, *p_yh, *p_woh, *p_cath, *p_wprh;
    cudaGetSymbolAddress((void**)&p_zx, g_zx);
    cudaGetSymbolAddress((void**)&p_hbuf, g_hbuf);
    cudaGetSymbolAddress((void**)&p_hbuf2, g_hbuf2);
    cudaGetSymbolAddress((void**)&p_xh, g_xh);
    cudaGetSymbolAddress((void**)&p_wip, g_wip_h);
    cudaGetSymbolAddress((void**)&p_yh, g_yh);
    cudaGetSymbolAddress((void**)&p_woh, g_woh);
    cudaGetSymbolAddress((void**)&p_cath, g_cath);
    cudaGetSymbolAddress((void**)&p_wprh, g_wprh);

    cudaFuncSetAttribute(gemm_hmma, cudaFuncAttributeMaxDynamicSharedMemorySize, G_SMEM);

    const size_t XSZ  = (size_t)M_ROWS * DMODEL;
    const size_t WIPS = (size_t)DINPROJ_PAD * DMODEL;
    const size_t YSZ  = (size_t)M_ROWS * DINNER;
    const size_t WOS  = (size_t)DMODEL * DINNER;

    // 0) converts needed before in_proj
    cvt_x_kernel<<<(int)(XSZ / 8 / 256), 256>>>(x);
    cvt_w_kernel<<<(int)((WIPS / 8 + 255) / 256), 256>>>(f_in_proj_w, p_wip,        DINPROJ * DMODEL / 8, (int)(WIPS / 8));
    cvt_w_kernel<<<(int)((WIPS / 8 + 255) / 256), 256>>>(b_in_proj_w, p_wip + WIPS, DINPROJ * DMODEL / 8, (int)(WIPS / 8));
    cvt_w_kernel<<<(int)(WOS / 8 / 256), 256>>>(f_out_proj_w, p_woh,       (int)(WOS / 8), (int)(WOS / 8));
    cvt_w_kernel<<<(int)(WOS / 8 / 256), 256>>>(b_out_proj_w, p_woh + WOS, (int)(WOS / 8), (int)(WOS / 8));

    // 1) in_proj GEMMs merged over z: (2048,1024)@(4352,1024)^T -> g_zx
    {
        dim3 grid(DINPROJ_PAD / 128, M_ROWS / 128, 2);
        gemm_hmma<<<grid, 256, G_SMEM>>>(p_xh, XSZ, p_wip, WIPS, p_zx, (size_t)M_ROWS * DINPROJ,
                                         DMODEL, DMODEL, DMODEL, DINPROJ, DINPROJ, 0);
    }

    // deferred convert (needed only by step 6)
    cvt_w_kernel<<<(int)(WOS / 8 / 256), 256>>>(proj_w, p_wprh, (int)(WOS / 8), (int)(WOS / 8));

    // 1b) fp32 recompute of dt columns + dt/dA
    fix_dt_kernel<<<2 * M_ROWS, 256>>>(x, f_in_proj_w, b_in_proj_w);
    dt_kernel<<<(2 * M_ROWS * NHEADS + 255) / 256, 256>>>(f_dt_bias, f_A_log, b_dt_bias, b_A_log);

    // 2) conv + silu
    conv_silu<<<(2 * M_ROWS * (CONVDIM / 4) + 255) / 256, 256>>>(f_conv_w, f_conv_b, b_conv_w, b_conv_b);

    // 3) scan (smem staged)
    scan_kernel<<<128, 256>>>();

    // 4) gate + rmsnorm -> fp16
    gate_rms<<<2 * M_ROWS, 256>>>(f_D, f_rms_w, b_D, b_rms_w);

    // 5) out_proj GEMMs merged over z (BN=128, verified), fused concat
    {
        dim3 grid(DMODEL / 128, M_ROWS / 128, 2);
        gemm_hmma<<<grid, 256, G_SMEM>>>(p_yh, YSZ, p_woh, WOS, (float*)nullptr, 0,
                                         DINNER, DINNER, DINNER, DMODEL, DMODEL, 1);
    }

    // 6) final proj GEMM, split-K=2 over z: K halves -> g_hbuf / g_hbuf2
    //    z offsets: A += z*1024 (col offset in K), B += z*1024, C: hbuf vs hbuf2
    {
        dim3 grid(DMODEL / 128, M_ROWS / 128, 2);
        gemm_hmma<<<grid, 256, G_SMEM>>>(p_cath, 1024, p_wprh, 1024,
                                         p_hbuf, (size_t)(p_hbuf2 - p_hbuf),
                                         DMODEL, DINNER, DINNER, DMODEL, DMODEL, 0);
    }

    // 7) residual + LayerNorm (sums split-K partials)
    ln_kernel<<<M_ROWS, 256>>>(x, proj_b, ln_w, ln_b, out);
}

// round 14
// speedup vs baseline: 1.0381x; 1.0008x over previous
#include <cuda_runtime.h>
#include <cuda_fp16.h>
#include <math.h>
#include <stdint.h>

#define L_SEQ   1024
#define BATCH   2
#define DMODEL  1024
#define DINNER  2048
#define NHEADS  32
#define HEADDIM 64
#define DSTATE  64
#define CONVDIM 2176
#define DINPROJ 4256
#define DINPROJ_PAD 4352
#define M_ROWS  2048   // BATCH * L_SEQ

// ===================== scratch (device globals) =============================
__device__ float g_zx[2][M_ROWS * DINPROJ];
__device__ float g_xbc[2][M_ROWS * CONVDIM];
__device__ float g_dt[2][M_ROWS * NHEADS];
__device__ float g_dA[2][M_ROWS * NHEADS];
__device__ float g_y[2][M_ROWS * DINNER];
__device__ float g_hbuf[M_ROWS * DMODEL];
__device__ float g_hbuf2[M_ROWS * DMODEL];           // split-K partial

__device__ __half g_xh[2][M_ROWS * DMODEL];          // dir0 = x, dir1 = flip(x)
__device__ __half g_wip_h[2][DINPROJ_PAD * DMODEL];  // in_proj weights (padded rows)
__device__ __half g_yh[2][M_ROWS * DINNER];          // gated/normed y
__device__ __half g_woh[2][DMODEL * DINNER];         // out_proj weights
__device__ __half g_cath[M_ROWS * DINNER];           // concat(fwd, flip(bwd)), fp16
__device__ __half g_wprh[DMODEL * DINNER];           // final proj weights

// ===================== small helpers ========================================
__device__ __forceinline__ uint32_t h2_as_u32(__half2 h) {
    uint32_t u;
    *(__half2*)&u = h;
    return u;
}
__device__ __forceinline__ uint32_t smem_u32(const void* p) {
    uint32_t a;
    asm("{ .reg .u64 t; cvta.to.shared.u64 t, %1; cvt.u32.u64 %0, t; }" : "=r"(a) : "l"(p));
    return a;
}
__device__ __forceinline__ void cp_async16(uint32_t s, const void* g) {
    asm volatile("cp.async.cg.shared.global [%0], [%1], 16;" :: "r"(s), "l"(g));
}
__device__ __forceinline__ void cp_async4(uint32_t s, const void* g) {
    asm volatile("cp.async.ca.shared.global [%0], [%1], 4;" :: "r"(s), "l"(g));
}
__device__ __forceinline__ void cp_commit() { asm volatile("cp.async.commit_group;" ::: "memory"); }
__device__ __forceinline__ void ldmatrix4(uint32_t& r0, uint32_t& r1, uint32_t& r2, uint32_t& r3, uint32_t a) {
    asm volatile("ldmatrix.sync.aligned.m8n8.x4.shared.b16 {%0,%1,%2,%3}, [%4];"
                 : "=r"(r0), "=r"(r1), "=r"(r2), "=r"(r3) : "r"(a));
}
__device__ __forceinline__ void mma16816(float* c, const uint32_t* a, const uint32_t* b) {
    asm volatile("mma.sync.aligned.m16n8k16.row.col.f32.f16.f16.f32 "
                 "{%0,%1,%2,%3}, {%4,%5,%6,%7}, {%8,%9}, {%0,%1,%2,%3};"
                 : "+f"(c[0]), "+f"(c[1]), "+f"(c[2]), "+f"(c[3])
                 : "r"(a[0]), "r"(a[1]), "r"(a[2]), "r"(a[3]), "r"(b[0]), "r"(b[1]));
}
__device__ __forceinline__ int fliprow(int r) { return ((r >> 10) << 10) + (1023 - (r & 1023)); }

// ===================== fp32 -> fp16 converts (8 elems/thread) ==============
__global__ void cvt_x_kernel(const float* __restrict__ x) {
    int idx = blockIdx.x * blockDim.x + threadIdx.x;     // 8-elem group
    if (idx >= M_ROWS * DMODEL / 8) return;
    int row = idx >> 7, c8 = idx & 127;
    const float4* s = (const float4*)(x) + idx * 2;
    float4 v0 = s[0], v1 = s[1];
    uint4 o;
    o.x = h2_as_u32(__floats2half2_rn(v0.x, v0.y));
    o.y = h2_as_u32(__floats2half2_rn(v0.z, v0.w));
    o.z = h2_as_u32(__floats2half2_rn(v1.x, v1.y));
    o.w = h2_as_u32(__floats2half2_rn(v1.z, v1.w));
    ((uint4*)g_xh[0])[idx] = o;
    ((uint4*)g_xh[1])[fliprow(row) * 128 + c8] = o;
}

__global__ void cvt_w_kernel(const float* __restrict__ w, __half* __restrict__ dst,
                             int n8src, int n8tot) {
    int idx = blockIdx.x * blockDim.x + threadIdx.x;
    if (idx >= n8tot) return;
    uint4 o;
    if (idx < n8src) {
        const float4* s = (const float4*)(w) + idx * 2;
        float4 v0 = s[0], v1 = s[1];
        o.x = h2_as_u32(__floats2half2_rn(v0.x, v0.y));
        o.y = h2_as_u32(__floats2half2_rn(v0.z, v0.w));
        o.z = h2_as_u32(__floats2half2_rn(v1.x, v1.y));
        o.w = h2_as_u32(__floats2half2_rn(v1.z, v1.w));
    } else {
        o = make_uint4(0, 0, 0, 0);
    }
    ((uint4*)dst)[idx] = o;
}

// ===================== HMMA fp16 GEMM (3-stage, 2 CTAs/SM, dbuf frags) ======
#define KT 64
#define RS2 144                        // bytes per smem row (64 halves + 8 pad)
#define A_ST_BYTES (128 * RS2)         // 18432
#define ST_BYTES   (2 * A_ST_BYTES)    // 36864 per stage
#define NSTAGE 3
#define G_SMEM (NSTAGE * ST_BYTES)     // 110592 -> 2 CTAs/SM

struct Frag { uint32_t A[2][4]; uint32_t B[8][2]; };

__device__ __forceinline__ void load_frags(uint32_t so, int k16,
        const uint32_t* a_off, const uint32_t* b_off, Frag& f) {
#pragma unroll
    for (int mi = 0; mi < 2; mi++)
        ldmatrix4(f.A[mi][0], f.A[mi][1], f.A[mi][2], f.A[mi][3], so + a_off[mi] + k16 * 32);
#pragma unroll
    for (int nj = 0; nj < 4; nj++) {
        uint32_t r0, r1, r2, r3;
        ldmatrix4(r0, r1, r2, r3, so + b_off[nj] + k16 * 32);
        f.B[2 * nj][0] = r0;     f.B[2 * nj][1] = r1;
        f.B[2 * nj + 1][0] = r2; f.B[2 * nj + 1][1] = r3;
    }
}

// ldA/ldB = row strides of A/B (may exceed K when split-K slices a wider matrix)
__global__ __launch_bounds__(256, 2) void gemm_hmma(
    const __half* __restrict__ A0, size_t strideA,
    const __half* __restrict__ B0, size_t strideB,
    float* __restrict__ C0, size_t strideC,
    int K, int ldA, int ldB, int Nreal, int ldc, int emode)
{
    extern __shared__ char smem[];
    const uint32_t sb = smem_u32(smem);
    const int tid = threadIdx.x;
    const int lane = tid & 31;
    const int warp = tid >> 5;
    const int z = blockIdx.z;
    const __half* A = A0 + (size_t)z * strideA;
    const __half* B = B0 + (size_t)z * strideB;
    float* C = C0 + (size_t)z * strideC;
    const int bm = blockIdx.y * 128;
    const int bn = blockIdx.x * 128;
    const int wm = (warp & 3) * 32;
    const int wn = (warp >> 2) * 64;
    const int T = K / KT;

    auto load_stage = [&](int t, int s) {
        const uint32_t so = sb + (uint32_t)s * ST_BYTES;
        const int k0 = t * KT;
#pragma unroll
        for (int it = 0; it < 4; it++) {
            int id = tid + (it << 8);
            int r = id >> 3, ck = id & 7;
            uint32_t sm = so + r * RS2 + ck * 16;
            cp_async16(sm, A + (size_t)(bm + r) * ldA + k0 + ck * 8);
            cp_async16(sm + A_ST_BYTES, B + (size_t)(bn + r) * ldB + k0 + ck * 8);
        }
    };

    float acc[2][8][4];
#pragma unroll
    for (int i = 0; i < 2; i++)
#pragma unroll
        for (int j = 0; j < 8; j++)
#pragma unroll
            for (int q = 0; q < 4; q++) acc[i][j][q] = 0.f;

    load_stage(0, 0); cp_commit();
    load_stage(1, 1); cp_commit();

    uint32_t a_off[2], b_off[4];
#pragma unroll
    for (int mi = 0; mi < 2; mi++)
        a_off[mi] = (wm + mi * 16 + (lane & 15)) * RS2 + ((lane >> 4) << 4);
#pragma unroll
    for (int nj = 0; nj < 4; nj++)
        b_off[nj] = (uint32_t)(wn + nj * 16 + (lane & 7) + ((lane >> 4) << 3)) * RS2
                  + (((lane >> 3) & 1) << 4) + A_ST_BYTES;

    Frag fr[2];
    int slot = 0;
#pragma unroll 1
    for (int t = 0; t < T; t++) {
        asm volatile("cp.async.wait_group 1;" ::: "memory");
        __syncthreads();
        if (t + 2 < T) {
            int ns = slot + 2; if (ns >= 3) ns -= 3;
            load_stage(t + 2, ns);
        }
        cp_commit();

        const uint32_t so = sb + (uint32_t)slot * ST_BYTES;
        load_frags(so, 0, a_off, b_off, fr[0]);
#pragma unroll
        for (int k16 = 0; k16 < 4; k16++) {
            if (k16 < 3) load_frags(so, k16 + 1, a_off, b_off, fr[(k16 + 1) & 1]);
            Frag& f = fr[k16 & 1];
#pragma unroll
            for (int mi = 0; mi < 2; mi++)
#pragma unroll
                for (int ni = 0; ni < 8; ni++)
                    mma16816(acc[mi][ni], f.A[mi], f.B[ni]);
        }
        if (++slot == 3) slot = 0;
    }

    if (emode == 0) {
#pragma unroll
        for (int mi = 0; mi < 2; mi++) {
            int row = bm + wm + mi * 16 + (lane >> 2);
#pragma unroll
            for (int ni = 0; ni < 8; ni++) {
                int col = bn + wn + ni * 8 + ((lane & 3) << 1);
                if (col < Nreal) {
                    *(float2*)&C[(size_t)row * ldc + col] = make_float2(acc[mi][ni][0], acc[mi][ni][1]);
                    *(float2*)&C[(size_t)(row + 8) * ldc + col] = make_float2(acc[mi][ni][2], acc[mi][ni][3]);
                }
            }
        }
    } else {
        // fused concat: fp16 store with row-flip for z==1, col offset z*1024
#pragma unroll
        for (int mi = 0; mi < 2; mi++) {
            int r0 = bm + wm + mi * 16 + (lane >> 2);
            int r1 = r0 + 8;
            int cr0 = z ? fliprow(r0) : r0;
            int cr1 = z ? fliprow(r1) : r1;
#pragma unroll
            for (int ni = 0; ni < 8; ni++) {
                int col = bn + wn + ni * 8 + ((lane & 3) << 1) + (z << 10);
                __half2 h0 = __floats2half2_rn(acc[mi][ni][0], acc[mi][ni][1]);
                __half2 h1 = __floats2half2_rn(acc[mi][ni][2], acc[mi][ni][3]);
                *(__half2*)&g_cath[(size_t)cr0 * DINNER + col] = h0;
                *(__half2*)&g_cath[(size_t)cr1 * DINNER + col] = h1;
            }
        }
    }
}

// ===================== fp32 recompute of dt columns (verified) ==============
__global__ __launch_bounds__(256) void fix_dt_kernel(const float* __restrict__ x,
        const float* __restrict__ fw, const float* __restrict__ bw) {
    __shared__ float xs[DMODEL];
    int blk = blockIdx.x;
    int dir = blk >> 11;
    int row = blk & 2047;
    int srow = dir ? fliprow(row) : row;
    ((float4*)xs)[threadIdx.x] = ((const float4*)(x + (size_t)srow * DMODEL))[threadIdx.x];
    __syncthreads();
    int warp = threadIdx.x >> 5, lane = threadIdx.x & 31;
    const float* w = dir ? bw : fw;
#pragma unroll
    for (int hh = 0; hh < 4; hh++) {
        int h = warp * 4 + hh;
        const float4* wr = (const float4*)(w + (size_t)(DINNER + CONVDIM + h) * DMODEL);
        const float4* xv = (const float4*)xs;
        float s = 0.f;
#pragma unroll
        for (int j = 0; j < 8; j++) {
            int i = lane + (j << 5);
            float4 a = xv[i], b = wr[i];
            s = fmaf(a.x, b.x, s); s = fmaf(a.y, b.y, s);
            s = fmaf(a.z, b.z, s); s = fmaf(a.w, b.w, s);
        }
#pragma unroll
        for (int o = 16; o; o >>= 1) s += __shfl_xor_sync(0xffffffffu, s, o);
        if (lane == 0) g_zx[dir][(size_t)row * DINPROJ + (DINNER + CONVDIM) + h] = s;
    }
}

// ===================== dt / dA (verified) ===================================
__global__ void dt_kernel(const float* __restrict__ f_dtb, const float* __restrict__ f_alog,
                          const float* __restrict__ b_dtb, const float* __restrict__ b_alog) {
    int idx = blockIdx.x * blockDim.x + threadIdx.x;
    if (idx >= 2 * M_ROWS * NHEADS) return;
    int h = idx & 31;
    int r = idx >> 5;
    int dir = r >> 11;
    int row = r & 2047;
    const float* db = dir ? b_dtb : f_dtb;
    const float* al = dir ? b_alog : f_alog;
    float xr = g_zx[dir][(size_t)row * DINPROJ + (DINNER + CONVDIM) + h] + db[h];
    float dt = (xr > 20.f) ? xr : log1pf(expf(xr));
    float A = -expf(al[h]);
    g_dt[dir][row * NHEADS + h] = dt;
    g_dA[dir][row * NHEADS + h] = expf(dt * A);
}

// ===================== depthwise conv + silu (float4, verified) =============
__global__ void conv_silu(const float* __restrict__ fw, const float* __restrict__ fb,
                          const float* __restrict__ bw, const float* __restrict__ bb) {
    int idx = blockIdx.x * blockDim.x + threadIdx.x;   // float4 column groups
    if (idx >= 2 * M_ROWS * (CONVDIM / 4)) return;
    int c4 = idx % (CONVDIM / 4);
    int r = idx / (CONVDIM / 4);
    int dir = r >> 11;
    int row = r & 2047;
    int t = row & 1023;
    int c = c4 * 4;
    const float* w = dir ? bw : fw;
    const float* bias = dir ? bb : fb;
    const float* zx = g_zx[dir];
    float4 acc = *(const float4*)(bias + c);
#pragma unroll
    for (int j = 0; j < 4; j++) {
        int tj = t - 3 + j;
        if (tj >= 0) {
            float4 wv = *(const float4*)(w + j * CONVDIM + c);
            float4 xv = *(const float4*)(zx + (size_t)(row - 3 + j) * DINPROJ + DINNER + c);
            acc.x = fmaf(wv.x, xv.x, acc.x); acc.y = fmaf(wv.y, xv.y, acc.y);
            acc.z = fmaf(wv.z, xv.z, acc.z); acc.w = fmaf(wv.w, xv.w, acc.w);
        }
    }
    acc.x /= (1.f + expf(-acc.x)); acc.y /= (1.f + expf(-acc.y));
    acc.z /= (1.f + expf(-acc.z)); acc.w /= (1.f + expf(-acc.w));
    *(float4*)(&g_xbc[dir][(size_t)row * CONVDIM + c]) = acc;
}

// ===================== SSM scan (verified config) ===========================
#define SCH 8   // taus per chunk
__global__ __launch_bounds__(256) void scan_kernel() {
    __shared__ float sBC[2][SCH][160];   // 8 groups of 16 floats padded to 20
    __shared__ float sX[2][SCH][64];
    __shared__ float sS[2][SCH][2];      // [0]=dA [1]=dt

    int blk = blockIdx.x;
    int dir = blk >> 6;
    int b = (blk >> 5) & 1;
    int h = blk & 31;
    int t = threadIdx.x;
    int p = t >> 2;
    int s = t & 3;

    const float* xbc = g_xbc[dir] + (size_t)(b * L_SEQ) * CONVDIM;
    const float* dtb = g_dt[dir] + (size_t)(b * L_SEQ) * NHEADS + h;
    const float* dAb = g_dA[dir] + (size_t)(b * L_SEQ) * NHEADS + h;
    float* yout = g_y[dir] + (size_t)(b * L_SEQ) * DINNER + h * HEADDIM + p;

    auto prefetch = [&](int cc) {
        int bf = cc & 1;
#pragma unroll
        for (int i = 0; i < 2; i++) {
            int op = t + (i << 8);
            if (op < 384) {
                int tau = op / 48, j = op - tau * 48;
                int gtau = cc * SCH + tau;
                if (j < 32) {
                    int g = j >> 2;
                    cp_async16(smem_u32(&sBC[bf][tau][g * 20 + (j & 3) * 4]),
                               xbc + (size_t)gtau * CONVDIM + DINNER + j * 4);
                } else {
                    int jj = j - 32;
                    cp_async16(smem_u32(&sX[bf][tau][jj * 4]),
                               xbc + (size_t)gtau * CONVDIM + h * HEADDIM + jj * 4);
                }
            }
        }
        if (t < 16) {
            int tau = t >> 1;
            int gtau = cc * SCH + tau;
            const float* src = (t & 1) ? (dtb + gtau * NHEADS) : (dAb + gtau * NHEADS);
            cp_async4(smem_u32(&sS[bf][tau][t & 1]), src);
        }
    };

    float st[16];
#pragma unroll
    for (int i = 0; i < 16; i++) st[i] = 0.f;

    prefetch(0); cp_commit();
    prefetch(1); cp_commit();

#pragma unroll 1
    for (int cc = 0; cc < L_SEQ / SCH; cc++) {
        asm volatile("cp.async.wait_group 1;" ::: "memory");
        __syncthreads();
        int bf = cc & 1;
#pragma unroll
        for (int tl = 0; tl < SCH; tl++) {
            float dAv = sS[bf][tl][0];
            float dtv = sS[bf][tl][1];
            float xv  = sX[bf][tl][p];
            float coef = dtv * xv;
            const float4* Bp = (const float4*)&sBC[bf][tl][s * 20];
            const float4* Cp = (const float4*)&sBC[bf][tl][(4 + s) * 20];
            float4 B0 = Bp[0], B1 = Bp[1], B2 = Bp[2], B3 = Bp[3];
            float4 C0 = Cp[0], C1 = Cp[1], C2 = Cp[2], C3 = Cp[3];
            float acc = 0.f;
            st[ 0] = fmaf(st[ 0], dAv, coef * B0.x); acc = fmaf(st[ 0], C0.x, acc);
            st[ 1] = fmaf(st[ 1], dAv, coef * B0.y); acc = fmaf(st[ 1], C0.y, acc);
            st[ 2] = fmaf(st[ 2], dAv, coef * B0.z); acc = fmaf(st[ 2], C0.z, acc);
            st[ 3] = fmaf(st[ 3], dAv, coef * B0.w); acc = fmaf(st[ 3], C0.w, acc);
            st[ 4] = fmaf(st[ 4], dAv, coef * B1.x); acc = fmaf(st[ 4], C1.x, acc);
            st[ 5] = fmaf(st[ 5], dAv, coef * B1.y); acc = fmaf(st[ 5], C1.y, acc);
            st[ 6] = fmaf(st[ 6], dAv, coef * B1.z); acc = fmaf(st[ 6], C1.z, acc);
            st[ 7] = fmaf(st[ 7], dAv, coef * B1.w); acc = fmaf(st[ 7], C1.w, acc);
            st[ 8] = fmaf(st[ 8], dAv, coef * B2.x); acc = fmaf(st[ 8], C2.x, acc);
            st[ 9] = fmaf(st[ 9], dAv, coef * B2.y); acc = fmaf(st[ 9], C2.y, acc);
            st[10] = fmaf(st[10], dAv, coef * B2.z); acc = fmaf(st[10], C2.z, acc);
            st[11] = fmaf(st[11], dAv, coef * B2.w); acc = fmaf(st[11], C2.w, acc);
            st[12] = fmaf(st[12], dAv, coef * B3.x); acc = fmaf(st[12], C3.x, acc);
            st[13] = fmaf(st[13], dAv, coef * B3.y); acc = fmaf(st[13], C3.y, acc);
            st[14] = fmaf(st[14], dAv, coef * B3.z); acc = fmaf(st[14], C3.z, acc);
            st[15] = fmaf(st[15], dAv, coef * B3.w); acc = fmaf(st[15], C3.w, acc);
            acc += __shfl_xor_sync(0xffffffffu, acc, 1);
            acc += __shfl_xor_sync(0xffffffffu, acc, 2);
            if (s == 0) yout[(size_t)(cc * SCH + tl) * DINNER] = acc;
        }
        __syncthreads();
        if (cc + 2 < L_SEQ / SCH) prefetch(cc + 2);
        cp_commit();
    }
}

// ===================== gate + RMSNorm -> fp16 (float4) ======================
__global__ __launch_bounds__(256) void gate_rms(const float* __restrict__ fD, const float* __restrict__ frms,
                                                const float* __restrict__ bD, const float* __restrict__ brms) {
    int blk = blockIdx.x;
    int dir = blk >> 11;
    int row = blk & 2047;
    const float* Dp = dir ? bD : fD;
    const float* rw = dir ? brms : frms;
    const float4* zr = (const float4*)(g_zx[dir] + (size_t)row * DINPROJ);
    const float4* xr = (const float4*)(g_xbc[dir] + (size_t)row * CONVDIM);
    const float4* yr = (const float4*)(g_y[dir] + (size_t)row * DINNER);

    float vals[8];
    float ss = 0.f;
#pragma unroll
    for (int i = 0; i < 2; i++) {
        int g = threadIdx.x + (i << 8);
        float4 y4 = yr[g], z4 = zr[g], x4 = xr[g];
        float Dv = Dp[(g * 4) >> 6];
        float yv, zv;
        yv = fmaf(Dv, x4.x, y4.x); zv = z4.x; yv *= zv / (1.f + expf(-zv)); vals[i*4+0] = yv; ss = fmaf(yv, yv, ss);
        yv = fmaf(Dv, x4.y, y4.y); zv = z4.y; yv *= zv / (1.f + expf(-zv)); vals[i*4+1] = yv; ss = fmaf(yv, yv, ss);
        yv = fmaf(Dv, x4.z, y4.z); zv = z4.z; yv *= zv / (1.f + expf(-zv)); vals[i*4+2] = yv; ss = fmaf(yv, yv, ss);
        yv = fmaf(Dv, x4.w, y4.w); zv = z4.w; yv *= zv / (1.f + expf(-zv)); vals[i*4+3] = yv; ss = fmaf(yv, yv, ss);
    }
    __shared__ float red[8];
    __shared__ float s_scale;
#pragma unroll
    for (int o = 16; o; o >>= 1) ss += __shfl_xor_sync(0xffffffffu, ss, o);
    if ((threadIdx.x & 31) == 0) red[threadIdx.x >> 5] = ss;
    __syncthreads();
    if (threadIdx.x == 0) {
        float tot = 0.f;
#pragma unroll
        for (int i = 0; i < 8; i++) tot += red[i];
        s_scale = rsqrtf(tot / (float)DINNER + 1e-5f);
    }
    __syncthreads();
    float sc = s_scale;
#pragma unroll
    for (int i = 0; i < 2; i++) {
        int g = threadIdx.x + (i << 8);
        const float4 w4 = ((const float4*)rw)[g];
        float o0 = vals[i*4+0] * sc * w4.x;
        float o1 = vals[i*4+1] * sc * w4.y;
        float o2 = vals[i*4+2] * sc * w4.z;
        float o3 = vals[i*4+3] * sc * w4.w;
        uint2 st;
        st.x = h2_as_u32(__floats2half2_rn(o0, o1));
        st.y = h2_as_u32(__floats2half2_rn(o2, o3));
        ((uint2*)(g_yh[dir] + (size_t)row * DINNER))[g] = st;
    }
}

// ===================== residual + LayerNorm (adds split-K partials) =========
__global__ __launch_bounds__(256) void ln_kernel(const float* __restrict__ x,
        const float* __restrict__ pb, const float* __restrict__ lw,
        const float* __restrict__ lb, float* __restrict__ out) {
    int row = blockIdx.x;
    const float* hr  = g_hbuf  + (size_t)row * DMODEL;
    const float* hr2 = g_hbuf2 + (size_t)row * DMODEL;
    const float* xr = x + (size_t)row * DMODEL;
    float v[4];
    float sum = 0.f;
#pragma unroll
    for (int i = 0; i < 4; i++) {
        int c = threadIdx.x + (i << 8);
        v[i] = (hr[c] + hr2[c]) + xr[c] + pb[c];
        sum += v[i];
    }
    __shared__ float red[8];
    __shared__ float s_mu, s_inv;
#pragma unroll
    for (int o = 16; o; o >>= 1) sum += __shfl_xor_sync(0xffffffffu, sum, o);
    if ((threadIdx.x & 31) == 0) red[threadIdx.x >> 5] = sum;
    __syncthreads();
    if (threadIdx.x == 0) {
        float tot = 0.f;
#pragma unroll
        for (int i = 0; i < 8; i++) tot += red[i];
        s_mu = tot / (float)DMODEL;
    }
    __syncthreads();
    float mu = s_mu;
    float vs = 0.f;
#pragma unroll
    for (int i = 0; i < 4; i++) { float d = v[i] - mu; vs = fmaf(d, d, vs); }
#pragma unroll
    for (int o = 16; o; o >>= 1) vs += __shfl_xor_sync(0xffffffffu, vs, o);
    if ((threadIdx.x & 31) == 0) red[threadIdx.x >> 5] = vs;
    __syncthreads();
    if (threadIdx.x == 0) {
        float tot = 0.f;
#pragma unroll
        for (int i = 0; i < 8; i++) tot += red[i];
        s_inv = rsqrtf(tot / (float)DMODEL + 1e-5f);
    }
    __syncthreads();
    float inv = s_inv;
#pragma unroll
    for (int i = 0; i < 4; i++) {
        int c = threadIdx.x + (i << 8);
        out[(size_t)row * DMODEL + c] = (v[i] - mu) * inv * lw[c] + lb[c];
    }
}

// ===================== host orchestration ===================================
extern "C" void kernel_launch(void* const* d_in, const int* in_sizes, int n_in,
                              void* d_out, int out_size) {
    const float* x            = (const float*)d_in[0];
    const float* f_in_proj_w  = (const float*)d_in[1];
    const float* f_conv_w     = (const float*)d_in[2];
    const float* f_conv_b     = (const float*)d_in[3];
    const float* f_dt_bias    = (const float*)d_in[4];
    const float* f_A_log      = (const float*)d_in[5];
    const float* f_D          = (const float*)d_in[6];
    const float* f_rms_w      = (const float*)d_in[7];
    const float* f_out_proj_w = (const float*)d_in[8];
    const float* b_in_proj_w  = (const float*)d_in[9];
    const float* b_conv_w     = (const float*)d_in[10];
    const float* b_conv_b     = (const float*)d_in[11];
    const float* b_dt_bias    = (const float*)d_in[12];
    const float* b_A_log      = (const float*)d_in[13];
    const float* b_D          = (const float*)d_in[14];
    const float* b_rms_w      = (const float*)d_in[15];
    const float* b_out_proj_w = (const float*)d_in[16];
    const float* proj_w       = (const float*)d_in[17];
    const float* proj_b       = (const float*)d_in[18];
    const float* ln_w         = (const float*)d_in[19];
    const float* ln_b         = (const float*)d_in[20];
    float* out = (float*)d_out;

    float *p_zx, *p_hbuf, *p_hbuf2;
    __half *p_xh, *p_wip, *p_yh, *p_woh, *p_cath, *p_wprh;
    cudaGetSymbolAddress((void**)&p_zx, g_zx);
    cudaGetSymbolAddress((void**)&p_hbuf, g_hbuf);
    cudaGetSymbolAddress((void**)&p_hbuf2, g_hbuf2);
    cudaGetSymbolAddress((void**)&p_xh, g_xh);
    cudaGetSymbolAddress((void**)&p_wip, g_wip_h);
    cudaGetSymbolAddress((void**)&p_yh, g_yh);
    cudaGetSymbolAddress((void**)&p_woh, g_woh);
    cudaGetSymbolAddress((void**)&p_cath, g_cath);
    cudaGetSymbolAddress((void**)&p_wprh, g_wprh);

    cudaFuncSetAttribute(gemm_hmma, cudaFuncAttributeMaxDynamicSharedMemorySize, G_SMEM);

    const size_t XSZ  = (size_t)M_ROWS * DMODEL;
    const size_t WIPS = (size_t)DINPROJ_PAD * DMODEL;
    const size_t YSZ  = (size_t)M_ROWS * DINNER;
    const size_t WOS  = (size_t)DMODEL * DINNER;

    // 0) converts needed before in_proj
    cvt_x_kernel<<<(int)(XSZ / 8 / 256), 256>>>(x);
    cvt_w_kernel<<<(int)((WIPS / 8 + 255) / 256), 256>>>(f_in_proj_w, p_wip,        DINPROJ * DMODEL / 8, (int)(WIPS / 8));
    cvt_w_kernel<<<(int)((WIPS / 8 + 255) / 256), 256>>>(b_in_proj_w, p_wip + WIPS, DINPROJ * DMODEL / 8, (int)(WIPS / 8));
    cvt_w_kernel<<<(int)(WOS / 8 / 256), 256>>>(f_out_proj_w, p_woh,       (int)(WOS / 8), (int)(WOS / 8));
    cvt_w_kernel<<<(int)(WOS / 8 / 256), 256>>>(b_out_proj_w, p_woh + WOS, (int)(WOS / 8), (int)(WOS / 8));

    // 1) in_proj GEMMs merged over z: (2048,1024)@(4352,1024)^T -> g_zx
    {
        dim3 grid(DINPROJ_PAD / 128, M_ROWS / 128, 2);
        gemm_hmma<<<grid, 256, G_SMEM>>>(p_xh, XSZ, p_wip, WIPS, p_zx, (size_t)M_ROWS * DINPROJ,
                                         DMODEL, DMODEL, DMODEL, DINPROJ, DINPROJ, 0);
    }

    // deferred convert (needed only by step 6)
    cvt_w_kernel<<<(int)(WOS / 8 / 256), 256>>>(proj_w, p_wprh, (int)(WOS / 8), (int)(WOS / 8));

    // 1b) fp32 recompute of dt columns + dt/dA
    fix_dt_kernel<<<2 * M_ROWS, 256>>>(x, f_in_proj_w, b_in_proj_w);
    dt_kernel<<<(2 * M_ROWS * NHEADS + 255) / 256, 256>>>(f_dt_bias, f_A_log, b_dt_bias, b_A_log);

    // 2) conv + silu
    conv_silu<<<(2 * M_ROWS * (CONVDIM / 4) + 255) / 256, 256>>>(f_conv_w, f_conv_b, b_conv_w, b_conv_b);

    // 3) scan (smem staged)
    scan_kernel<<<128, 256>>>();

    // 4) gate + rmsnorm -> fp16
    gate_rms<<<2 * M_ROWS, 256>>>(f_D, f_rms_w, b_D, b_rms_w);

    // 5) out_proj GEMMs merged over z (BN=128, verified), fused concat
    {
        dim3 grid(DMODEL / 128, M_ROWS / 128, 2);
        gemm_hmma<<<grid, 256, G_SMEM>>>(p_yh, YSZ, p_woh, WOS, (float*)nullptr, 0,
                                         DINNER, DINNER, DINNER, DMODEL, DMODEL, 1);
    }

    // 6) final proj GEMM, split-K=2 over z: K halves -> g_hbuf / g_hbuf2
    {
        dim3 grid(DMODEL / 128, M_ROWS / 128, 2);
        gemm_hmma<<<grid, 256, G_SMEM>>>(p_cath, 1024, p_wprh, 1024,
                                         p_hbuf, (size_t)(p_hbuf2 - p_hbuf),
                                         DMODEL, DINNER, DINNER, DMODEL, DMODEL, 0);
    }

    // 7) residual + LayerNorm (sums split-K partials)
    ln_kernel<<<M_ROWS, 256>>>(x, proj_b, ln_w, ln_b, out);
}

// round 15
// speedup vs baseline: 1.0644x; 1.0254x over previous
#include <cuda_runtime.h>
#include <cuda_fp16.h>
#include <math.h>
#include <stdint.h>

#define L_SEQ   1024
#define BATCH   2
#define DMODEL  1024
#define DINNER  2048
#define NHEADS  32
#define HEADDIM 64
#define DSTATE  64
#define CONVDIM 2176
#define DINPROJ 4256
#define DINPROJ_PAD 4352
#define M_ROWS  2048   // BATCH * L_SEQ

// ===================== scratch (device globals) =============================
__device__ __half g_zxh[2][M_ROWS * DINPROJ];        // in_proj output, fp16
__device__ float g_dtraw[2][M_ROWS * NHEADS];        // fp32 dt dot products
__device__ float g_xbc[2][M_ROWS * CONVDIM];
__device__ float g_dt[2][M_ROWS * NHEADS];
__device__ float g_dA[2][M_ROWS * NHEADS];
__device__ float g_y[2][M_ROWS * DINNER];
__device__ float g_hbuf[M_ROWS * DMODEL];
__device__ float g_hbuf2[M_ROWS * DMODEL];           // split-K partial

__device__ __half g_xh[2][M_ROWS * DMODEL];          // dir0 = x, dir1 = flip(x)
__device__ __half g_wip_h[2][DINPROJ_PAD * DMODEL];  // in_proj weights (padded rows)
__device__ __half g_yh[2][M_ROWS * DINNER];          // gated/normed y
__device__ __half g_woh[2][DMODEL * DINNER];         // out_proj weights
__device__ __half g_cath[M_ROWS * DINNER];           // concat(fwd, flip(bwd)), fp16
__device__ __half g_wprh[DMODEL * DINNER];           // final proj weights

// ===================== small helpers ========================================
__device__ __forceinline__ uint32_t h2_as_u32(__half2 h) {
    uint32_t u;
    *(__half2*)&u = h;
    return u;
}
__device__ __forceinline__ uint32_t smem_u32(const void* p) {
    uint32_t a;
    asm("{ .reg .u64 t; cvta.to.shared.u64 t, %1; cvt.u32.u64 %0, t; }" : "=r"(a) : "l"(p));
    return a;
}
__device__ __forceinline__ void cp_async16(uint32_t s, const void* g) {
    asm volatile("cp.async.cg.shared.global [%0], [%1], 16;" :: "r"(s), "l"(g));
}
__device__ __forceinline__ void cp_async4(uint32_t s, const void* g) {
    asm volatile("cp.async.ca.shared.global [%0], [%1], 4;" :: "r"(s), "l"(g));
}
__device__ __forceinline__ void cp_commit() { asm volatile("cp.async.commit_group;" ::: "memory"); }
__device__ __forceinline__ void ldmatrix4(uint32_t& r0, uint32_t& r1, uint32_t& r2, uint32_t& r3, uint32_t a) {
    asm volatile("ldmatrix.sync.aligned.m8n8.x4.shared.b16 {%0,%1,%2,%3}, [%4];"
                 : "=r"(r0), "=r"(r1), "=r"(r2), "=r"(r3) : "r"(a));
}
__device__ __forceinline__ void mma16816(float* c, const uint32_t* a, const uint32_t* b) {
    asm volatile("mma.sync.aligned.m16n8k16.row.col.f32.f16.f16.f32 "
                 "{%0,%1,%2,%3}, {%4,%5,%6,%7}, {%8,%9}, {%0,%1,%2,%3};"
                 : "+f"(c[0]), "+f"(c[1]), "+f"(c[2]), "+f"(c[3])
                 : "r"(a[0]), "r"(a[1]), "r"(a[2]), "r"(a[3]), "r"(b[0]), "r"(b[1]));
}
__device__ __forceinline__ int fliprow(int r) { return ((r >> 10) << 10) + (1023 - (r & 1023)); }

// ===================== fp32 -> fp16 converts (8 elems/thread) ==============
__global__ void cvt_x_kernel(const float* __restrict__ x) {
    int idx = blockIdx.x * blockDim.x + threadIdx.x;     // 8-elem group
    if (idx >= M_ROWS * DMODEL / 8) return;
    int row = idx >> 7, c8 = idx & 127;
    const float4* s = (const float4*)(x) + idx * 2;
    float4 v0 = s[0], v1 = s[1];
    uint4 o;
    o.x = h2_as_u32(__floats2half2_rn(v0.x, v0.y));
    o.y = h2_as_u32(__floats2half2_rn(v0.z, v0.w));
    o.z = h2_as_u32(__floats2half2_rn(v1.x, v1.y));
    o.w = h2_as_u32(__floats2half2_rn(v1.z, v1.w));
    ((uint4*)g_xh[0])[idx] = o;
    ((uint4*)g_xh[1])[fliprow(row) * 128 + c8] = o;
}

__global__ void cvt_w_kernel(const float* __restrict__ w, __half* __restrict__ dst,
                             int n8src, int n8tot) {
    int idx = blockIdx.x * blockDim.x + threadIdx.x;
    if (idx >= n8tot) return;
    uint4 o;
    if (idx < n8src) {
        const float4* s = (const float4*)(w) + idx * 2;
        float4 v0 = s[0], v1 = s[1];
        o.x = h2_as_u32(__floats2half2_rn(v0.x, v0.y));
        o.y = h2_as_u32(__floats2half2_rn(v0.z, v0.w));
        o.z = h2_as_u32(__floats2half2_rn(v1.x, v1.y));
        o.w = h2_as_u32(__floats2half2_rn(v1.z, v1.w));
    } else {
        o = make_uint4(0, 0, 0, 0);
    }
    ((uint4*)dst)[idx] = o;
}

// ===================== HMMA fp16 GEMM (3-stage, 2 CTAs/SM, dbuf frags) ======
// emode 0: fp32 C. emode 1: fp16 concat w/ flip. emode 2: fp16 C (C0 is __half*).
#define KT 64
#define RS2 144                        // bytes per smem row (64 halves + 8 pad)
#define A_ST_BYTES (128 * RS2)         // 18432
#define ST_BYTES   (2 * A_ST_BYTES)    // 36864 per stage
#define NSTAGE 3
#define G_SMEM (NSTAGE * ST_BYTES)     // 110592 -> 2 CTAs/SM

struct Frag { uint32_t A[2][4]; uint32_t B[8][2]; };

__device__ __forceinline__ void load_frags(uint32_t so, int k16,
        const uint32_t* a_off, const uint32_t* b_off, Frag& f) {
#pragma unroll
    for (int mi = 0; mi < 2; mi++)
        ldmatrix4(f.A[mi][0], f.A[mi][1], f.A[mi][2], f.A[mi][3], so + a_off[mi] + k16 * 32);
#pragma unroll
    for (int nj = 0; nj < 4; nj++) {
        uint32_t r0, r1, r2, r3;
        ldmatrix4(r0, r1, r2, r3, so + b_off[nj] + k16 * 32);
        f.B[2 * nj][0] = r0;     f.B[2 * nj][1] = r1;
        f.B[2 * nj + 1][0] = r2; f.B[2 * nj + 1][1] = r3;
    }
}

__global__ __launch_bounds__(256, 2) void gemm_hmma(
    const __half* __restrict__ A0, size_t strideA,
    const __half* __restrict__ B0, size_t strideB,
    float* __restrict__ C0, size_t strideC,
    int K, int ldA, int ldB, int Nreal, int ldc, int emode)
{
    extern __shared__ char smem[];
    const uint32_t sb = smem_u32(smem);
    const int tid = threadIdx.x;
    const int lane = tid & 31;
    const int warp = tid >> 5;
    const int z = blockIdx.z;
    const __half* A = A0 + (size_t)z * strideA;
    const __half* B = B0 + (size_t)z * strideB;
    const int bm = blockIdx.y * 128;
    const int bn = blockIdx.x * 128;
    const int wm = (warp & 3) * 32;
    const int wn = (warp >> 2) * 64;
    const int T = K / KT;

    auto load_stage = [&](int t, int s) {
        const uint32_t so = sb + (uint32_t)s * ST_BYTES;
        const int k0 = t * KT;
#pragma unroll
        for (int it = 0; it < 4; it++) {
            int id = tid + (it << 8);
            int r = id >> 3, ck = id & 7;
            uint32_t sm = so + r * RS2 + ck * 16;
            cp_async16(sm, A + (size_t)(bm + r) * ldA + k0 + ck * 8);
            cp_async16(sm + A_ST_BYTES, B + (size_t)(bn + r) * ldB + k0 + ck * 8);
        }
    };

    float acc[2][8][4];
#pragma unroll
    for (int i = 0; i < 2; i++)
#pragma unroll
        for (int j = 0; j < 8; j++)
#pragma unroll
            for (int q = 0; q < 4; q++) acc[i][j][q] = 0.f;

    load_stage(0, 0); cp_commit();
    load_stage(1, 1); cp_commit();

    uint32_t a_off[2], b_off[4];
#pragma unroll
    for (int mi = 0; mi < 2; mi++)
        a_off[mi] = (wm + mi * 16 + (lane & 15)) * RS2 + ((lane >> 4) << 4);
#pragma unroll
    for (int nj = 0; nj < 4; nj++)
        b_off[nj] = (uint32_t)(wn + nj * 16 + (lane & 7) + ((lane >> 4) << 3)) * RS2
                  + (((lane >> 3) & 1) << 4) + A_ST_BYTES;

    Frag fr[2];
    int slot = 0;
#pragma unroll 1
    for (int t = 0; t < T; t++) {
        asm volatile("cp.async.wait_group 1;" ::: "memory");
        __syncthreads();
        if (t + 2 < T) {
            int ns = slot + 2; if (ns >= 3) ns -= 3;
            load_stage(t + 2, ns);
        }
        cp_commit();

        const uint32_t so = sb + (uint32_t)slot * ST_BYTES;
        load_frags(so, 0, a_off, b_off, fr[0]);
#pragma unroll
        for (int k16 = 0; k16 < 4; k16++) {
            if (k16 < 3) load_frags(so, k16 + 1, a_off, b_off, fr[(k16 + 1) & 1]);
            Frag& f = fr[k16 & 1];
#pragma unroll
            for (int mi = 0; mi < 2; mi++)
#pragma unroll
                for (int ni = 0; ni < 8; ni++)
                    mma16816(acc[mi][ni], f.A[mi], f.B[ni]);
        }
        if (++slot == 3) slot = 0;
    }

    if (emode == 0) {
        float* C = C0 + (size_t)z * strideC;
#pragma unroll
        for (int mi = 0; mi < 2; mi++) {
            int row = bm + wm + mi * 16 + (lane >> 2);
#pragma unroll
            for (int ni = 0; ni < 8; ni++) {
                int col = bn + wn + ni * 8 + ((lane & 3) << 1);
                if (col < Nreal) {
                    *(float2*)&C[(size_t)row * ldc + col] = make_float2(acc[mi][ni][0], acc[mi][ni][1]);
                    *(float2*)&C[(size_t)(row + 8) * ldc + col] = make_float2(acc[mi][ni][2], acc[mi][ni][3]);
                }
            }
        }
    } else if (emode == 2) {
        // fp16 C output
        __half* Ch = (__half*)C0 + (size_t)z * strideC;
#pragma unroll
        for (int mi = 0; mi < 2; mi++) {
            int row = bm + wm + mi * 16 + (lane >> 2);
#pragma unroll
            for (int ni = 0; ni < 8; ni++) {
                int col = bn + wn + ni * 8 + ((lane & 3) << 1);
                if (col < Nreal) {
                    *(__half2*)&Ch[(size_t)row * ldc + col] = __floats2half2_rn(acc[mi][ni][0], acc[mi][ni][1]);
                    *(__half2*)&Ch[(size_t)(row + 8) * ldc + col] = __floats2half2_rn(acc[mi][ni][2], acc[mi][ni][3]);
                }
            }
        }
    } else {
        // fused concat: fp16 store with row-flip for z==1, col offset z*1024
#pragma unroll
        for (int mi = 0; mi < 2; mi++) {
            int r0 = bm + wm + mi * 16 + (lane >> 2);
            int r1 = r0 + 8;
            int cr0 = z ? fliprow(r0) : r0;
            int cr1 = z ? fliprow(r1) : r1;
#pragma unroll
            for (int ni = 0; ni < 8; ni++) {
                int col = bn + wn + ni * 8 + ((lane & 3) << 1) + (z << 10);
                __half2 h0 = __floats2half2_rn(acc[mi][ni][0], acc[mi][ni][1]);
                __half2 h1 = __floats2half2_rn(acc[mi][ni][2], acc[mi][ni][3]);
                *(__half2*)&g_cath[(size_t)cr0 * DINNER + col] = h0;
                *(__half2*)&g_cath[(size_t)cr1 * DINNER + col] = h1;
            }
        }
    }
}

// ===================== fp32 recompute of dt columns -> g_dtraw ==============
__global__ __launch_bounds__(256) void fix_dt_kernel(const float* __restrict__ x,
        const float* __restrict__ fw, const float* __restrict__ bw) {
    __shared__ float xs[DMODEL];
    int blk = blockIdx.x;
    int dir = blk >> 11;
    int row = blk & 2047;
    int srow = dir ? fliprow(row) : row;
    ((float4*)xs)[threadIdx.x] = ((const float4*)(x + (size_t)srow * DMODEL))[threadIdx.x];
    __syncthreads();
    int warp = threadIdx.x >> 5, lane = threadIdx.x & 31;
    const float* w = dir ? bw : fw;
#pragma unroll
    for (int hh = 0; hh < 4; hh++) {
        int h = warp * 4 + hh;
        const float4* wr = (const float4*)(w + (size_t)(DINNER + CONVDIM + h) * DMODEL);
        const float4* xv = (const float4*)xs;
        float s = 0.f;
#pragma unroll
        for (int j = 0; j < 8; j++) {
            int i = lane + (j << 5);
            float4 a = xv[i], b = wr[i];
            s = fmaf(a.x, b.x, s); s = fmaf(a.y, b.y, s);
            s = fmaf(a.z, b.z, s); s = fmaf(a.w, b.w, s);
        }
#pragma unroll
        for (int o = 16; o; o >>= 1) s += __shfl_xor_sync(0xffffffffu, s, o);
        if (lane == 0) g_dtraw[dir][row * NHEADS + h] = s;
    }
}

// ===================== dt / dA (reads g_dtraw) ==============================
__global__ void dt_kernel(const float* __restrict__ f_dtb, const float* __restrict__ f_alog,
                          const float* __restrict__ b_dtb, const float* __restrict__ b_alog) {
    int idx = blockIdx.x * blockDim.x + threadIdx.x;
    if (idx >= 2 * M_ROWS * NHEADS) return;
    int h = idx & 31;
    int r = idx >> 5;
    int dir = r >> 11;
    int row = r & 2047;
    const float* db = dir ? b_dtb : f_dtb;
    const float* al = dir ? b_alog : f_alog;
    float xr = g_dtraw[dir][row * NHEADS + h] + db[h];
    float dt = (xr > 20.f) ? xr : log1pf(expf(xr));
    float A = -expf(al[h]);
    g_dt[dir][row * NHEADS + h] = dt;
    g_dA[dir][row * NHEADS + h] = expf(dt * A);
}

// ===================== depthwise conv + silu (fp16 input) ===================
__global__ void conv_silu(const float* __restrict__ fw, const float* __restrict__ fb,
                          const float* __restrict__ bw, const float* __restrict__ bb) {
    int idx = blockIdx.x * blockDim.x + threadIdx.x;   // 4-col groups
    if (idx >= 2 * M_ROWS * (CONVDIM / 4)) return;
    int c4 = idx % (CONVDIM / 4);
    int r = idx / (CONVDIM / 4);
    int dir = r >> 11;
    int row = r & 2047;
    int t = row & 1023;
    int c = c4 * 4;
    const float* w = dir ? bw : fw;
    const float* bias = dir ? bb : fb;
    const __half* zx = g_zxh[dir];
    float4 acc = *(const float4*)(bias + c);
#pragma unroll
    for (int j = 0; j < 4; j++) {
        int tj = t - 3 + j;
        if (tj >= 0) {
            float4 wv = *(const float4*)(w + j * CONVDIM + c);
            const __half2* xp = (const __half2*)(zx + (size_t)(row - 3 + j) * DINPROJ + DINNER + c);
            float2 f0 = __half22float2(xp[0]);
            float2 f1 = __half22float2(xp[1]);
            acc.x = fmaf(wv.x, f0.x, acc.x); acc.y = fmaf(wv.y, f0.y, acc.y);
            acc.z = fmaf(wv.z, f1.x, acc.z); acc.w = fmaf(wv.w, f1.y, acc.w);
        }
    }
    acc.x /= (1.f + expf(-acc.x)); acc.y /= (1.f + expf(-acc.y));
    acc.z /= (1.f + expf(-acc.z)); acc.w /= (1.f + expf(-acc.w));
    *(float4*)(&g_xbc[dir][(size_t)row * CONVDIM + c]) = acc;
}

// ===================== SSM scan (verified config) ===========================
#define SCH 8   // taus per chunk
__global__ __launch_bounds__(256) void scan_kernel() {
    __shared__ float sBC[2][SCH][160];   // 8 groups of 16 floats padded to 20
    __shared__ float sX[2][SCH][64];
    __shared__ float sS[2][SCH][2];      // [0]=dA [1]=dt

    int blk = blockIdx.x;
    int dir = blk >> 6;
    int b = (blk >> 5) & 1;
    int h = blk & 31;
    int t = threadIdx.x;
    int p = t >> 2;
    int s = t & 3;

    const float* xbc = g_xbc[dir] + (size_t)(b * L_SEQ) * CONVDIM;
    const float* dtb = g_dt[dir] + (size_t)(b * L_SEQ) * NHEADS + h;
    const float* dAb = g_dA[dir] + (size_t)(b * L_SEQ) * NHEADS + h;
    float* yout = g_y[dir] + (size_t)(b * L_SEQ) * DINNER + h * HEADDIM + p;

    auto prefetch = [&](int cc) {
        int bf = cc & 1;
#pragma unroll
        for (int i = 0; i < 2; i++) {
            int op = t + (i << 8);
            if (op < 384) {
                int tau = op / 48, j = op - tau * 48;
                int gtau = cc * SCH + tau;
                if (j < 32) {
                    int g = j >> 2;
                    cp_async16(smem_u32(&sBC[bf][tau][g * 20 + (j & 3) * 4]),
                               xbc + (size_t)gtau * CONVDIM + DINNER + j * 4);
                } else {
                    int jj = j - 32;
                    cp_async16(smem_u32(&sX[bf][tau][jj * 4]),
                               xbc + (size_t)gtau * CONVDIM + h * HEADDIM + jj * 4);
                }
            }
        }
        if (t < 16) {
            int tau = t >> 1;
            int gtau = cc * SCH + tau;
            const float* src = (t & 1) ? (dtb + gtau * NHEADS) : (dAb + gtau * NHEADS);
            cp_async4(smem_u32(&sS[bf][tau][t & 1]), src);
        }
    };

    float st[16];
#pragma unroll
    for (int i = 0; i < 16; i++) st[i] = 0.f;

    prefetch(0); cp_commit();
    prefetch(1); cp_commit();

#pragma unroll 1
    for (int cc = 0; cc < L_SEQ / SCH; cc++) {
        asm volatile("cp.async.wait_group 1;" ::: "memory");
        __syncthreads();
        int bf = cc & 1;
#pragma unroll
        for (int tl = 0; tl < SCH; tl++) {
            float dAv = sS[bf][tl][0];
            float dtv = sS[bf][tl][1];
            float xv  = sX[bf][tl][p];
            float coef = dtv * xv;
            const float4* Bp = (const float4*)&sBC[bf][tl][s * 20];
            const float4* Cp = (const float4*)&sBC[bf][tl][(4 + s) * 20];
            float4 B0 = Bp[0], B1 = Bp[1], B2 = Bp[2], B3 = Bp[3];
            float4 C0 = Cp[0], C1 = Cp[1], C2 = Cp[2], C3 = Cp[3];
            float acc = 0.f;
            st[ 0] = fmaf(st[ 0], dAv, coef * B0.x); acc = fmaf(st[ 0], C0.x, acc);
            st[ 1] = fmaf(st[ 1], dAv, coef * B0.y); acc = fmaf(st[ 1], C0.y, acc);
            st[ 2] = fmaf(st[ 2], dAv, coef * B0.z); acc = fmaf(st[ 2], C0.z, acc);
            st[ 3] = fmaf(st[ 3], dAv, coef * B0.w); acc = fmaf(st[ 3], C0.w, acc);
            st[ 4] = fmaf(st[ 4], dAv, coef * B1.x); acc = fmaf(st[ 4], C1.x, acc);
            st[ 5] = fmaf(st[ 5], dAv, coef * B1.y); acc = fmaf(st[ 5], C1.y, acc);
            st[ 6] = fmaf(st[ 6], dAv, coef * B1.z); acc = fmaf(st[ 6], C1.z, acc);
            st[ 7] = fmaf(st[ 7], dAv, coef * B1.w); acc = fmaf(st[ 7], C1.w, acc);
            st[ 8] = fmaf(st[ 8], dAv, coef * B2.x); acc = fmaf(st[ 8], C2.x, acc);
            st[ 9] = fmaf(st[ 9], dAv, coef * B2.y); acc = fmaf(st[ 9], C2.y, acc);
            st[10] = fmaf(st[10], dAv, coef * B2.z); acc = fmaf(st[10], C2.z, acc);
            st[11] = fmaf(st[11], dAv, coef * B2.w); acc = fmaf(st[11], C2.w, acc);
            st[12] = fmaf(st[12], dAv, coef * B3.x); acc = fmaf(st[12], C3.x, acc);
            st[13] = fmaf(st[13], dAv, coef * B3.y); acc = fmaf(st[13], C3.y, acc);
            st[14] = fmaf(st[14], dAv, coef * B3.z); acc = fmaf(st[14], C3.z, acc);
            st[15] = fmaf(st[15], dAv, coef * B3.w); acc = fmaf(st[15], C3.w, acc);
            acc += __shfl_xor_sync(0xffffffffu, acc, 1);
            acc += __shfl_xor_sync(0xffffffffu, acc, 2);
            if (s == 0) yout[(size_t)(cc * SCH + tl) * DINNER] = acc;
        }
        __syncthreads();
        if (cc + 2 < L_SEQ / SCH) prefetch(cc + 2);
        cp_commit();
    }
}

// ===================== gate + RMSNorm -> fp16 (z from fp16) =================
__global__ __launch_bounds__(256) void gate_rms(const float* __restrict__ fD, const float* __restrict__ frms,
                                                const float* __restrict__ bD, const float* __restrict__ brms) {
    int blk = blockIdx.x;
    int dir = blk >> 11;
    int row = blk & 2047;
    const float* Dp = dir ? bD : fD;
    const float* rw = dir ? brms : frms;
    const __half* zrow = g_zxh[dir] + (size_t)row * DINPROJ;
    const float4* xr = (const float4*)(g_xbc[dir] + (size_t)row * CONVDIM);
    const float4* yr = (const float4*)(g_y[dir] + (size_t)row * DINNER);

    float vals[8];
    float ss = 0.f;
#pragma unroll
    for (int i = 0; i < 2; i++) {
        int g = threadIdx.x + (i << 8);
        float4 y4 = yr[g], x4 = xr[g];
        const __half2* zp = (const __half2*)(zrow + g * 4);
        float2 z0 = __half22float2(zp[0]);
        float2 z1 = __half22float2(zp[1]);
        float Dv = Dp[(g * 4) >> 6];
        float yv, zv;
        yv = fmaf(Dv, x4.x, y4.x); zv = z0.x; yv *= zv / (1.f + expf(-zv)); vals[i*4+0] = yv; ss = fmaf(yv, yv, ss);
        yv = fmaf(Dv, x4.y, y4.y); zv = z0.y; yv *= zv / (1.f + expf(-zv)); vals[i*4+1] = yv; ss = fmaf(yv, yv, ss);
        yv = fmaf(Dv, x4.z, y4.z); zv = z1.x; yv *= zv / (1.f + expf(-zv)); vals[i*4+2] = yv; ss = fmaf(yv, yv, ss);
        yv = fmaf(Dv, x4.w, y4.w); zv = z1.y; yv *= zv / (1.f + expf(-zv)); vals[i*4+3] = yv; ss = fmaf(yv, yv, ss);
    }
    __shared__ float red[8];
    __shared__ float s_scale;
#pragma unroll
    for (int o = 16; o; o >>= 1) ss += __shfl_xor_sync(0xffffffffu, ss, o);
    if ((threadIdx.x & 31) == 0) red[threadIdx.x >> 5] = ss;
    __syncthreads();
    if (threadIdx.x == 0) {
        float tot = 0.f;
#pragma unroll
        for (int i = 0; i < 8; i++) tot += red[i];
        s_scale = rsqrtf(tot / (float)DINNER + 1e-5f);
    }
    __syncthreads();
    float sc = s_scale;
#pragma unroll
    for (int i = 0; i < 2; i++) {
        int g = threadIdx.x + (i << 8);
        const float4 w4 = ((const float4*)rw)[g];
        float o0 = vals[i*4+0] * sc * w4.x;
        float o1 = vals[i*4+1] * sc * w4.y;
        float o2 = vals[i*4+2] * sc * w4.z;
        float o3 = vals[i*4+3] * sc * w4.w;
        uint2 st;
        st.x = h2_as_u32(__floats2half2_rn(o0, o1));
        st.y = h2_as_u32(__floats2half2_rn(o2, o3));
        ((uint2*)(g_yh[dir] + (size_t)row * DINNER))[g] = st;
    }
}

// ===================== residual + LayerNorm (adds split-K partials) =========
__global__ __launch_bounds__(256) void ln_kernel(const float* __restrict__ x,
        const float* __restrict__ pb, const float* __restrict__ lw,
        const float* __restrict__ lb, float* __restrict__ out) {
    int row = blockIdx.x;
    const float* hr  = g_hbuf  + (size_t)row * DMODEL;
    const float* hr2 = g_hbuf2 + (size_t)row * DMODEL;
    const float* xr = x + (size_t)row * DMODEL;
    float v[4];
    float sum = 0.f;
#pragma unroll
    for (int i = 0; i < 4; i++) {
        int c = threadIdx.x + (i << 8);
        v[i] = (hr[c] + hr2[c]) + xr[c] + pb[c];
        sum += v[i];
    }
    __shared__ float red[8];
    __shared__ float s_mu, s_inv;
#pragma unroll
    for (int o = 16; o; o >>= 1) sum += __shfl_xor_sync(0xffffffffu, sum, o);
    if ((threadIdx.x & 31) == 0) red[threadIdx.x >> 5] = sum;
    __syncthreads();
    if (threadIdx.x == 0) {
        float tot = 0.f;
#pragma unroll
        for (int i = 0; i < 8; i++) tot += red[i];
        s_mu = tot / (float)DMODEL;
    }
    __syncthreads();
    float mu = s_mu;
    float vs = 0.f;
#pragma unroll
    for (int i = 0; i < 4; i++) { float d = v[i] - mu; vs = fmaf(d, d, vs); }
#pragma unroll
    for (int o = 16; o; o >>= 1) vs += __shfl_xor_sync(0xffffffffu, vs, o);
    if ((threadIdx.x & 31) == 0) red[threadIdx.x >> 5] = vs;
    __syncthreads();
    if (threadIdx.x == 0) {
        float tot = 0.f;
#pragma unroll
        for (int i = 0; i < 8; i++) tot += red[i];
        s_inv = rsqrtf(tot / (float)DMODEL + 1e-5f);
    }
    __syncthreads();
    float inv = s_inv;
#pragma unroll
    for (int i = 0; i < 4; i++) {
        int c = threadIdx.x + (i << 8);
        out[(size_t)row * DMODEL + c] = (v[i] - mu) * inv * lw[c] + lb[c];
    }
}

// ===================== host orchestration ===================================
extern "C" void kernel_launch(void* const* d_in, const int* in_sizes, int n_in,
                              void* d_out, int out_size) {
    const float* x            = (const float*)d_in[0];
    const float* f_in_proj_w  = (const float*)d_in[1];
    const float* f_conv_w     = (const float*)d_in[2];
    const float* f_conv_b     = (const float*)d_in[3];
    const float* f_dt_bias    = (const float*)d_in[4];
    const float* f_A_log      = (const float*)d_in[5];
    const float* f_D          = (const float*)d_in[6];
    const float* f_rms_w      = (const float*)d_in[7];
    const float* f_out_proj_w = (const float*)d_in[8];
    const float* b_in_proj_w  = (const float*)d_in[9];
    const float* b_conv_w     = (const float*)d_in[10];
    const float* b_conv_b     = (const float*)d_in[11];
    const float* b_dt_bias    = (const float*)d_in[12];
    const float* b_A_log      = (const float*)d_in[13];
    const float* b_D          = (const float*)d_in[14];
    const float* b_rms_w      = (const float*)d_in[15];
    const float* b_out_proj_w = (const float*)d_in[16];
    const float* proj_w       = (const float*)d_in[17];
    const float* proj_b       = (const float*)d_in[18];
    const float* ln_w         = (const float*)d_in[19];
    const float* ln_b         = (const float*)d_in[20];
    float* out = (float*)d_out;

    float *p_hbuf, *p_hbuf2;
    __half *p_zxh, *p_xh, *p_wip, *p_yh, *p_woh, *p_cath, *p_wprh;
    cudaGetSymbolAddress((void**)&p_zxh, g_zxh);
    cudaGetSymbolAddress((void**)&p_hbuf, g_hbuf);
    cudaGetSymbolAddress((void**)&p_hbuf2, g_hbuf2);
    cudaGetSymbolAddress((void**)&p_xh, g_xh);
    cudaGetSymbolAddress((void**)&p_wip, g_wip_h);
    cudaGetSymbolAddress((void**)&p_yh, g_yh);
    cudaGetSymbolAddress((void**)&p_woh, g_woh);
    cudaGetSymbolAddress((void**)&p_cath, g_cath);
    cudaGetSymbolAddress((void**)&p_wprh, g_wprh);

    cudaFuncSetAttribute(gemm_hmma, cudaFuncAttributeMaxDynamicSharedMemorySize, G_SMEM);

    const size_t XSZ  = (size_t)M_ROWS * DMODEL;
    const size_t WIPS = (size_t)DINPROJ_PAD * DMODEL;
    const size_t YSZ  = (size_t)M_ROWS * DINNER;
    const size_t WOS  = (size_t)DMODEL * DINNER;

    // 0) converts needed before in_proj
    cvt_x_kernel<<<(int)(XSZ / 8 / 256), 256>>>(x);
    cvt_w_kernel<<<(int)((WIPS / 8 + 255) / 256), 256>>>(f_in_proj_w, p_wip,        DINPROJ * DMODEL / 8, (int)(WIPS / 8));
    cvt_w_kernel<<<(int)((WIPS / 8 + 255) / 256), 256>>>(b_in_proj_w, p_wip + WIPS, DINPROJ * DMODEL / 8, (int)(WIPS / 8));
    cvt_w_kernel<<<(int)(WOS / 8 / 256), 256>>>(f_out_proj_w, p_woh,       (int)(WOS / 8), (int)(WOS / 8));
    cvt_w_kernel<<<(int)(WOS / 8 / 256), 256>>>(b_out_proj_w, p_woh + WOS, (int)(WOS / 8), (int)(WOS / 8));

    // 1) in_proj GEMMs merged over z, fp16 output (emode 2) -> g_zxh
    {
        dim3 grid(DINPROJ_PAD / 128, M_ROWS / 128, 2);
        gemm_hmma<<<grid, 256, G_SMEM>>>(p_xh, XSZ, p_wip, WIPS,
                                         (float*)p_zxh, (size_t)M_ROWS * DINPROJ,
                                         DMODEL, DMODEL, DMODEL, DINPROJ, DINPROJ, 2);
    }

    // deferred convert (needed only by step 6)
    cvt_w_kernel<<<(int)(WOS / 8 / 256), 256>>>(proj_w, p_wprh, (int)(WOS / 8), (int)(WOS / 8));

    // 1b) fp32 dt dot products -> g_dtraw; dt/dA
    fix_dt_kernel<<<2 * M_ROWS, 256>>>(x, f_in_proj_w, b_in_proj_w);
    dt_kernel<<<(2 * M_ROWS * NHEADS + 255) / 256, 256>>>(f_dt_bias, f_A_log, b_dt_bias, b_A_log);

    // 2) conv + silu (fp16 input)
    conv_silu<<<(2 * M_ROWS * (CONVDIM / 4) + 255) / 256, 256>>>(f_conv_w, f_conv_b, b_conv_w, b_conv_b);

    // 3) scan (smem staged)
    scan_kernel<<<128, 256>>>();

    // 4) gate + rmsnorm -> fp16 (z read from fp16 zx)
    gate_rms<<<2 * M_ROWS, 256>>>(f_D, f_rms_w, b_D, b_rms_w);

    // 5) out_proj GEMMs merged over z (BN=128), fused concat
    {
        dim3 grid(DMODEL / 128, M_ROWS / 128, 2);
        gemm_hmma<<<grid, 256, G_SMEM>>>(p_yh, YSZ, p_woh, WOS, (float*)nullptr, 0,
                                         DINNER, DINNER, DINNER, DMODEL, DMODEL, 1);
    }

    // 6) final proj GEMM, split-K=2 over z: K halves -> g_hbuf / g_hbuf2
    {
        dim3 grid(DMODEL / 128, M_ROWS / 128, 2);
        gemm_hmma<<<grid, 256, G_SMEM>>>(p_cath, 1024, p_wprh, 1024,
                                         p_hbuf, (size_t)(p_hbuf2 - p_hbuf),
                                         DMODEL, DINNER, DINNER, DMODEL, DMODEL, 0);
    }

    // 7) residual + LayerNorm (sums split-K partials)
    ln_kernel<<<M_ROWS, 256>>>(x, proj_b, ln_w, ln_b, out);
}

// round 16
// speedup vs baseline: 1.0866x; 1.0208x over previous
#include <cuda_runtime.h>
#include <cuda_fp16.h>
#include <math.h>
#include <stdint.h>

#define L_SEQ   1024
#define BATCH   2
#define DMODEL  1024
#define DINNER  2048
#define NHEADS  32
#define HEADDIM 64
#define DSTATE  64
#define CONVDIM 2176
#define DINPROJ 4256
#define DINPROJ_PAD 4352
#define M_ROWS  2048   // BATCH * L_SEQ

// ===================== scratch (device globals) =============================
__device__ __half g_zxh[2][M_ROWS * DINPROJ];        // in_proj output, fp16
__device__ float g_dtraw[2][M_ROWS * NHEADS];        // fp32 dt dot products
__device__ float g_xbc[2][M_ROWS * CONVDIM];
__device__ float g_dt[2][M_ROWS * NHEADS];
__device__ float g_dA[2][M_ROWS * NHEADS];
__device__ float g_y[2][M_ROWS * DINNER];
__device__ float g_hbuf[M_ROWS * DMODEL];
__device__ float g_hbuf2[M_ROWS * DMODEL];           // split-K partial

__device__ __half g_xh[2][M_ROWS * DMODEL];          // dir0 = x, dir1 = flip(x)
__device__ __half g_wip_h[2][DINPROJ_PAD * DMODEL];  // in_proj weights (padded rows)
__device__ __half g_yh[2][M_ROWS * DINNER];          // gated/normed y
__device__ __half g_woh[2][DMODEL * DINNER];         // out_proj weights
__device__ __half g_cath[M_ROWS * DINNER];           // concat(fwd, flip(bwd)), fp16
__device__ __half g_wprh[DMODEL * DINNER];           // final proj weights

// ===================== small helpers ========================================
__device__ __forceinline__ uint32_t h2_as_u32(__half2 h) {
    uint32_t u;
    *(__half2*)&u = h;
    return u;
}
__device__ __forceinline__ uint32_t smem_u32(const void* p) {
    uint32_t a;
    asm("{ .reg .u64 t; cvta.to.shared.u64 t, %1; cvt.u32.u64 %0, t; }" : "=r"(a) : "l"(p));
    return a;
}
__device__ __forceinline__ void cp_async16(uint32_t s, const void* g) {
    asm volatile("cp.async.cg.shared.global [%0], [%1], 16;" :: "r"(s), "l"(g));
}
__device__ __forceinline__ void cp_async4(uint32_t s, const void* g) {
    asm volatile("cp.async.ca.shared.global [%0], [%1], 4;" :: "r"(s), "l"(g));
}
__device__ __forceinline__ void cp_commit() { asm volatile("cp.async.commit_group;" ::: "memory"); }
__device__ __forceinline__ void ldmatrix4(uint32_t& r0, uint32_t& r1, uint32_t& r2, uint32_t& r3, uint32_t a) {
    asm volatile("ldmatrix.sync.aligned.m8n8.x4.shared.b16 {%0,%1,%2,%3}, [%4];"
                 : "=r"(r0), "=r"(r1), "=r"(r2), "=r"(r3) : "r"(a));
}
__device__ __forceinline__ void mma16816(float* c, const uint32_t* a, const uint32_t* b) {
    asm volatile("mma.sync.aligned.m16n8k16.row.col.f32.f16.f16.f32 "
                 "{%0,%1,%2,%3}, {%4,%5,%6,%7}, {%8,%9}, {%0,%1,%2,%3};"
                 : "+f"(c[0]), "+f"(c[1]), "+f"(c[2]), "+f"(c[3])
                 : "r"(a[0]), "r"(a[1]), "r"(a[2]), "r"(a[3]), "r"(b[0]), "r"(b[1]));
}
__device__ __forceinline__ int fliprow(int r) { return ((r >> 10) << 10) + (1023 - (r & 1023)); }

// ===================== fp32 -> fp16 converts ================================
__global__ void cvt_x_kernel(const float* __restrict__ x) {
    int idx = blockIdx.x * blockDim.x + threadIdx.x;     // 8-elem group
    if (idx >= M_ROWS * DMODEL / 8) return;
    int row = idx >> 7, c8 = idx & 127;
    const float4* s = (const float4*)(x) + idx * 2;
    float4 v0 = s[0], v1 = s[1];
    uint4 o;
    o.x = h2_as_u32(__floats2half2_rn(v0.x, v0.y));
    o.y = h2_as_u32(__floats2half2_rn(v0.z, v0.w));
    o.z = h2_as_u32(__floats2half2_rn(v1.x, v1.y));
    o.w = h2_as_u32(__floats2half2_rn(v1.z, v1.w));
    ((uint4*)g_xh[0])[idx] = o;
    ((uint4*)g_xh[1])[fliprow(row) * 128 + c8] = o;
}

// All five weight tensors converted in ONE launch (segments are compile-time).
#define W8_WIP    (DINPROJ_PAD * DMODEL / 8)   // 557056 per dir (padded)
#define W8_WIPSRC (DINPROJ * DMODEL / 8)       // 544768 real groups
#define W8_WO     (DMODEL * DINNER / 8)        // 262144
#define W8_TOTAL  (2 * W8_WIP + 3 * W8_WO)

__global__ void cvt_allw_kernel(const float* __restrict__ fw, const float* __restrict__ bw,
                                const float* __restrict__ fo, const float* __restrict__ bo,
                                const float* __restrict__ pw) {
    int idx = blockIdx.x * blockDim.x + threadIdx.x;
    if (idx >= W8_TOTAL) return;
    const float* src;
    __half* dst;
    int local, n8src;
    if (idx < 2 * W8_WIP) {
        int d = idx >= W8_WIP;
        local = idx - d * W8_WIP;
        src = d ? bw : fw;
        dst = g_wip_h[d];
        n8src = W8_WIPSRC;
    } else {
        int j = idx - 2 * W8_WIP;
        int seg = j / W8_WO;
        local = j - seg * W8_WO;
        src = (seg == 0) ? fo : (seg == 1) ? bo : pw;
        dst = (seg == 0) ? g_woh[0] : (seg == 1) ? g_woh[1] : g_wprh;
        n8src = W8_WO;
    }
    uint4 o;
    if (local < n8src) {
        const float4* s = (const float4*)(src) + local * 2;
        float4 v0 = s[0], v1 = s[1];
        o.x = h2_as_u32(__floats2half2_rn(v0.x, v0.y));
        o.y = h2_as_u32(__floats2half2_rn(v0.z, v0.w));
        o.z = h2_as_u32(__floats2half2_rn(v1.x, v1.y));
        o.w = h2_as_u32(__floats2half2_rn(v1.z, v1.w));
    } else {
        o = make_uint4(0, 0, 0, 0);
    }
    ((uint4*)dst)[local] = o;
}

// ===================== HMMA fp16 GEMM (3-stage, 2 CTAs/SM, dbuf frags) ======
// emode 0: fp32 C. emode 1: fp16 concat w/ flip. emode 2: fp16 C (C0 is __half*).
#define KT 64
#define RS2 144                        // bytes per smem row (64 halves + 8 pad)
#define A_ST_BYTES (128 * RS2)         // 18432
#define ST_BYTES   (2 * A_ST_BYTES)    // 36864 per stage
#define NSTAGE 3
#define G_SMEM (NSTAGE * ST_BYTES)     // 110592 -> 2 CTAs/SM

struct Frag { uint32_t A[2][4]; uint32_t B[8][2]; };

__device__ __forceinline__ void load_frags(uint32_t so, int k16,
        const uint32_t* a_off, const uint32_t* b_off, Frag& f) {
#pragma unroll
    for (int mi = 0; mi < 2; mi++)
        ldmatrix4(f.A[mi][0], f.A[mi][1], f.A[mi][2], f.A[mi][3], so + a_off[mi] + k16 * 32);
#pragma unroll
    for (int nj = 0; nj < 4; nj++) {
        uint32_t r0, r1, r2, r3;
        ldmatrix4(r0, r1, r2, r3, so + b_off[nj] + k16 * 32);
        f.B[2 * nj][0] = r0;     f.B[2 * nj][1] = r1;
        f.B[2 * nj + 1][0] = r2; f.B[2 * nj + 1][1] = r3;
    }
}

__global__ __launch_bounds__(256, 2) void gemm_hmma(
    const __half* __restrict__ A0, size_t strideA,
    const __half* __restrict__ B0, size_t strideB,
    float* __restrict__ C0, size_t strideC,
    int K, int ldA, int ldB, int Nreal, int ldc, int emode)
{
    extern __shared__ char smem[];
    const uint32_t sb = smem_u32(smem);
    const int tid = threadIdx.x;
    const int lane = tid & 31;
    const int warp = tid >> 5;
    const int z = blockIdx.z;
    const __half* A = A0 + (size_t)z * strideA;
    const __half* B = B0 + (size_t)z * strideB;
    const int bm = blockIdx.y * 128;
    const int bn = blockIdx.x * 128;
    const int wm = (warp & 3) * 32;
    const int wn = (warp >> 2) * 64;
    const int T = K / KT;

    auto load_stage = [&](int t, int s) {
        const uint32_t so = sb + (uint32_t)s * ST_BYTES;
        const int k0 = t * KT;
#pragma unroll
        for (int it = 0; it < 4; it++) {
            int id = tid + (it << 8);
            int r = id >> 3, ck = id & 7;
            uint32_t sm = so + r * RS2 + ck * 16;
            cp_async16(sm, A + (size_t)(bm + r) * ldA + k0 + ck * 8);
            cp_async16(sm + A_ST_BYTES, B + (size_t)(bn + r) * ldB + k0 + ck * 8);
        }
    };

    float acc[2][8][4];
#pragma unroll
    for (int i = 0; i < 2; i++)
#pragma unroll
        for (int j = 0; j < 8; j++)
#pragma unroll
            for (int q = 0; q < 4; q++) acc[i][j][q] = 0.f;

    load_stage(0, 0); cp_commit();
    load_stage(1, 1); cp_commit();

    uint32_t a_off[2], b_off[4];
#pragma unroll
    for (int mi = 0; mi < 2; mi++)
        a_off[mi] = (wm + mi * 16 + (lane & 15)) * RS2 + ((lane >> 4) << 4);
#pragma unroll
    for (int nj = 0; nj < 4; nj++)
        b_off[nj] = (uint32_t)(wn + nj * 16 + (lane & 7) + ((lane >> 4) << 3)) * RS2
                  + (((lane >> 3) & 1) << 4) + A_ST_BYTES;

    Frag fr[2];
    int slot = 0;
#pragma unroll 1
    for (int t = 0; t < T; t++) {
        asm volatile("cp.async.wait_group 1;" ::: "memory");
        __syncthreads();
        if (t + 2 < T) {
            int ns = slot + 2; if (ns >= 3) ns -= 3;
            load_stage(t + 2, ns);
        }
        cp_commit();

        const uint32_t so = sb + (uint32_t)slot * ST_BYTES;
        load_frags(so, 0, a_off, b_off, fr[0]);
#pragma unroll
        for (int k16 = 0; k16 < 4; k16++) {
            if (k16 < 3) load_frags(so, k16 + 1, a_off, b_off, fr[(k16 + 1) & 1]);
            Frag& f = fr[k16 & 1];
#pragma unroll
            for (int mi = 0; mi < 2; mi++)
#pragma unroll
                for (int ni = 0; ni < 8; ni++)
                    mma16816(acc[mi][ni], f.A[mi], f.B[ni]);
        }
        if (++slot == 3) slot = 0;
    }

    if (emode == 0) {
        float* C = C0 + (size_t)z * strideC;
#pragma unroll
        for (int mi = 0; mi < 2; mi++) {
            int row = bm + wm + mi * 16 + (lane >> 2);
#pragma unroll
            for (int ni = 0; ni < 8; ni++) {
                int col = bn + wn + ni * 8 + ((lane & 3) << 1);
                if (col < Nreal) {
                    *(float2*)&C[(size_t)row * ldc + col] = make_float2(acc[mi][ni][0], acc[mi][ni][1]);
                    *(float2*)&C[(size_t)(row + 8) * ldc + col] = make_float2(acc[mi][ni][2], acc[mi][ni][3]);
                }
            }
        }
    } else if (emode == 2) {
        __half* Ch = (__half*)C0 + (size_t)z * strideC;
#pragma unroll
        for (int mi = 0; mi < 2; mi++) {
            int row = bm + wm + mi * 16 + (lane >> 2);
#pragma unroll
            for (int ni = 0; ni < 8; ni++) {
                int col = bn + wn + ni * 8 + ((lane & 3) << 1);
                if (col < Nreal) {
                    *(__half2*)&Ch[(size_t)row * ldc + col] = __floats2half2_rn(acc[mi][ni][0], acc[mi][ni][1]);
                    *(__half2*)&Ch[(size_t)(row + 8) * ldc + col] = __floats2half2_rn(acc[mi][ni][2], acc[mi][ni][3]);
                }
            }
        }
    } else {
        // fused concat: fp16 store with row-flip for z==1, col offset z*1024
#pragma unroll
        for (int mi = 0; mi < 2; mi++) {
            int r0 = bm + wm + mi * 16 + (lane >> 2);
            int r1 = r0 + 8;
            int cr0 = z ? fliprow(r0) : r0;
            int cr1 = z ? fliprow(r1) : r1;
#pragma unroll
            for (int ni = 0; ni < 8; ni++) {
                int col = bn + wn + ni * 8 + ((lane & 3) << 1) + (z << 10);
                __half2 h0 = __floats2half2_rn(acc[mi][ni][0], acc[mi][ni][1]);
                __half2 h1 = __floats2half2_rn(acc[mi][ni][2], acc[mi][ni][3]);
                *(__half2*)&g_cath[(size_t)cr0 * DINNER + col] = h0;
                *(__half2*)&g_cath[(size_t)cr1 * DINNER + col] = h1;
            }
        }
    }
}

// ===================== fp32 recompute of dt columns -> g_dtraw ==============
__global__ __launch_bounds__(256) void fix_dt_kernel(const float* __restrict__ x,
        const float* __restrict__ fw, const float* __restrict__ bw) {
    __shared__ float xs[DMODEL];
    int blk = blockIdx.x;
    int dir = blk >> 11;
    int row = blk & 2047;
    int srow = dir ? fliprow(row) : row;
    ((float4*)xs)[threadIdx.x] = ((const float4*)(x + (size_t)srow * DMODEL))[threadIdx.x];
    __syncthreads();
    int warp = threadIdx.x >> 5, lane = threadIdx.x & 31;
    const float* w = dir ? bw : fw;
#pragma unroll
    for (int hh = 0; hh < 4; hh++) {
        int h = warp * 4 + hh;
        const float4* wr = (const float4*)(w + (size_t)(DINNER + CONVDIM + h) * DMODEL);
        const float4* xv = (const float4*)xs;
        float s = 0.f;
#pragma unroll
        for (int j = 0; j < 8; j++) {
            int i = lane + (j << 5);
            float4 a = xv[i], b = wr[i];
            s = fmaf(a.x, b.x, s); s = fmaf(a.y, b.y, s);
            s = fmaf(a.z, b.z, s); s = fmaf(a.w, b.w, s);
        }
#pragma unroll
        for (int o = 16; o; o >>= 1) s += __shfl_xor_sync(0xffffffffu, s, o);
        if (lane == 0) g_dtraw[dir][row * NHEADS + h] = s;
    }
}

// ===================== dt / dA (reads g_dtraw) ==============================
__global__ void dt_kernel(const float* __restrict__ f_dtb, const float* __restrict__ f_alog,
                          const float* __restrict__ b_dtb, const float* __restrict__ b_alog) {
    int idx = blockIdx.x * blockDim.x + threadIdx.x;
    if (idx >= 2 * M_ROWS * NHEADS) return;
    int h = idx & 31;
    int r = idx >> 5;
    int dir = r >> 11;
    int row = r & 2047;
    const float* db = dir ? b_dtb : f_dtb;
    const float* al = dir ? b_alog : f_alog;
    float xr = g_dtraw[dir][row * NHEADS + h] + db[h];
    float dt = (xr > 20.f) ? xr : log1pf(expf(xr));
    float A = -expf(al[h]);
    g_dt[dir][row * NHEADS + h] = dt;
    g_dA[dir][row * NHEADS + h] = expf(dt * A);
}

// ===================== depthwise conv + silu (fp16 input) ===================
__global__ void conv_silu(const float* __restrict__ fw, const float* __restrict__ fb,
                          const float* __restrict__ bw, const float* __restrict__ bb) {
    int idx = blockIdx.x * blockDim.x + threadIdx.x;   // 4-col groups
    if (idx >= 2 * M_ROWS * (CONVDIM / 4)) return;
    int c4 = idx % (CONVDIM / 4);
    int r = idx / (CONVDIM / 4);
    int dir = r >> 11;
    int row = r & 2047;
    int t = row & 1023;
    int c = c4 * 4;
    const float* w = dir ? bw : fw;
    const float* bias = dir ? bb : fb;
    const __half* zx = g_zxh[dir];
    float4 acc = *(const float4*)(bias + c);
#pragma unroll
    for (int j = 0; j < 4; j++) {
        int tj = t - 3 + j;
        if (tj >= 0) {
            float4 wv = *(const float4*)(w + j * CONVDIM + c);
            const __half2* xp = (const __half2*)(zx + (size_t)(row - 3 + j) * DINPROJ + DINNER + c);
            float2 f0 = __half22float2(xp[0]);
            float2 f1 = __half22float2(xp[1]);
            acc.x = fmaf(wv.x, f0.x, acc.x); acc.y = fmaf(wv.y, f0.y, acc.y);
            acc.z = fmaf(wv.z, f1.x, acc.z); acc.w = fmaf(wv.w, f1.y, acc.w);
        }
    }
    acc.x /= (1.f + expf(-acc.x)); acc.y /= (1.f + expf(-acc.y));
    acc.z /= (1.f + expf(-acc.z)); acc.w /= (1.f + expf(-acc.w));
    *(float4*)(&g_xbc[dir][(size_t)row * CONVDIM + c]) = acc;
}

// ===================== SSM scan (verified config) ===========================
#define SCH 8   // taus per chunk
__global__ __launch_bounds__(256) void scan_kernel() {
    __shared__ float sBC[2][SCH][160];   // 8 groups of 16 floats padded to 20
    __shared__ float sX[2][SCH][64];
    __shared__ float sS[2][SCH][2];      // [0]=dA [1]=dt

    int blk = blockIdx.x;
    int dir = blk >> 6;
    int b = (blk >> 5) & 1;
    int h = blk & 31;
    int t = threadIdx.x;
    int p = t >> 2;
    int s = t & 3;

    const float* xbc = g_xbc[dir] + (size_t)(b * L_SEQ) * CONVDIM;
    const float* dtb = g_dt[dir] + (size_t)(b * L_SEQ) * NHEADS + h;
    const float* dAb = g_dA[dir] + (size_t)(b * L_SEQ) * NHEADS + h;
    float* yout = g_y[dir] + (size_t)(b * L_SEQ) * DINNER + h * HEADDIM + p;

    auto prefetch = [&](int cc) {
        int bf = cc & 1;
#pragma unroll
        for (int i = 0; i < 2; i++) {
            int op = t + (i << 8);
            if (op < 384) {
                int tau = op / 48, j = op - tau * 48;
                int gtau = cc * SCH + tau;
                if (j < 32) {
                    int g = j >> 2;
                    cp_async16(smem_u32(&sBC[bf][tau][g * 20 + (j & 3) * 4]),
                               xbc + (size_t)gtau * CONVDIM + DINNER + j * 4);
                } else {
                    int jj = j - 32;
                    cp_async16(smem_u32(&sX[bf][tau][jj * 4]),
                               xbc + (size_t)gtau * CONVDIM + h * HEADDIM + jj * 4);
                }
            }
        }
        if (t < 16) {
            int tau = t >> 1;
            int gtau = cc * SCH + tau;
            const float* src = (t & 1) ? (dtb + gtau * NHEADS) : (dAb + gtau * NHEADS);
            cp_async4(smem_u32(&sS[bf][tau][t & 1]), src);
        }
    };

    float st[16];
#pragma unroll
    for (int i = 0; i < 16; i++) st[i] = 0.f;

    prefetch(0); cp_commit();
    prefetch(1); cp_commit();

#pragma unroll 1
    for (int cc = 0; cc < L_SEQ / SCH; cc++) {
        asm volatile("cp.async.wait_group 1;" ::: "memory");
        __syncthreads();
        int bf = cc & 1;
#pragma unroll
        for (int tl = 0; tl < SCH; tl++) {
            float dAv = sS[bf][tl][0];
            float dtv = sS[bf][tl][1];
            float xv  = sX[bf][tl][p];
            float coef = dtv * xv;
            const float4* Bp = (const float4*)&sBC[bf][tl][s * 20];
            const float4* Cp = (const float4*)&sBC[bf][tl][(4 + s) * 20];
            float4 B0 = Bp[0], B1 = Bp[1], B2 = Bp[2], B3 = Bp[3];
            float4 C0 = Cp[0], C1 = Cp[1], C2 = Cp[2], C3 = Cp[3];
            float acc = 0.f;
            st[ 0] = fmaf(st[ 0], dAv, coef * B0.x); acc = fmaf(st[ 0], C0.x, acc);
            st[ 1] = fmaf(st[ 1], dAv, coef * B0.y); acc = fmaf(st[ 1], C0.y, acc);
            st[ 2] = fmaf(st[ 2], dAv, coef * B0.z); acc = fmaf(st[ 2], C0.z, acc);
            st[ 3] = fmaf(st[ 3], dAv, coef * B0.w); acc = fmaf(st[ 3], C0.w, acc);
            st[ 4] = fmaf(st[ 4], dAv, coef * B1.x); acc = fmaf(st[ 4], C1.x, acc);
            st[ 5] = fmaf(st[ 5], dAv, coef * B1.y); acc = fmaf(st[ 5], C1.y, acc);
            st[ 6] = fmaf(st[ 6], dAv, coef * B1.z); acc = fmaf(st[ 6], C1.z, acc);
            st[ 7] = fmaf(st[ 7], dAv, coef * B1.w); acc = fmaf(st[ 7], C1.w, acc);
            st[ 8] = fmaf(st[ 8], dAv, coef * B2.x); acc = fmaf(st[ 8], C2.x, acc);
            st[ 9] = fmaf(st[ 9], dAv, coef * B2.y); acc = fmaf(st[ 9], C2.y, acc);
            st[10] = fmaf(st[10], dAv, coef * B2.z); acc = fmaf(st[10], C2.z, acc);
            st[11] = fmaf(st[11], dAv, coef * B2.w); acc = fmaf(st[11], C2.w, acc);
            st[12] = fmaf(st[12], dAv, coef * B3.x); acc = fmaf(st[12], C3.x, acc);
            st[13] = fmaf(st[13], dAv, coef * B3.y); acc = fmaf(st[13], C3.y, acc);
            st[14] = fmaf(st[14], dAv, coef * B3.z); acc = fmaf(st[14], C3.z, acc);
            st[15] = fmaf(st[15], dAv, coef * B3.w); acc = fmaf(st[15], C3.w, acc);
            acc += __shfl_xor_sync(0xffffffffu, acc, 1);
            acc += __shfl_xor_sync(0xffffffffu, acc, 2);
            if (s == 0) yout[(size_t)(cc * SCH + tl) * DINNER] = acc;
        }
        __syncthreads();
        if (cc + 2 < L_SEQ / SCH) prefetch(cc + 2);
        cp_commit();
    }
}

// ===================== gate + RMSNorm -> fp16 (z from fp16) =================
__global__ __launch_bounds__(256) void gate_rms(const float* __restrict__ fD, const float* __restrict__ frms,
                                                const float* __restrict__ bD, const float* __restrict__ brms) {
    int blk = blockIdx.x;
    int dir = blk >> 11;
    int row = blk & 2047;
    const float* Dp = dir ? bD : fD;
    const float* rw = dir ? brms : frms;
    const __half* zrow = g_zxh[dir] + (size_t)row * DINPROJ;
    const float4* xr = (const float4*)(g_xbc[dir] + (size_t)row * CONVDIM);
    const float4* yr = (const float4*)(g_y[dir] + (size_t)row * DINNER);

    float vals[8];
    float ss = 0.f;
#pragma unroll
    for (int i = 0; i < 2; i++) {
        int g = threadIdx.x + (i << 8);
        float4 y4 = yr[g], x4 = xr[g];
        const __half2* zp = (const __half2*)(zrow + g * 4);
        float2 z0 = __half22float2(zp[0]);
        float2 z1 = __half22float2(zp[1]);
        float Dv = Dp[(g * 4) >> 6];
        float yv, zv;
        yv = fmaf(Dv, x4.x, y4.x); zv = z0.x; yv *= zv / (1.f + expf(-zv)); vals[i*4+0] = yv; ss = fmaf(yv, yv, ss);
        yv = fmaf(Dv, x4.y, y4.y); zv = z0.y; yv *= zv / (1.f + expf(-zv)); vals[i*4+1] = yv; ss = fmaf(yv, yv, ss);
        yv = fmaf(Dv, x4.z, y4.z); zv = z1.x; yv *= zv / (1.f + expf(-zv)); vals[i*4+2] = yv; ss = fmaf(yv, yv, ss);
        yv = fmaf(Dv, x4.w, y4.w); zv = z1.y; yv *= zv / (1.f + expf(-zv)); vals[i*4+3] = yv; ss = fmaf(yv, yv, ss);
    }
    __shared__ float red[8];
    __shared__ float s_scale;
#pragma unroll
    for (int o = 16; o; o >>= 1) ss += __shfl_xor_sync(0xffffffffu, ss, o);
    if ((threadIdx.x & 31) == 0) red[threadIdx.x >> 5] = ss;
    __syncthreads();
    if (threadIdx.x == 0) {
        float tot = 0.f;
#pragma unroll
        for (int i = 0; i < 8; i++) tot += red[i];
        s_scale = rsqrtf(tot / (float)DINNER + 1e-5f);
    }
    __syncthreads();
    float sc = s_scale;
#pragma unroll
    for (int i = 0; i < 2; i++) {
        int g = threadIdx.x + (i << 8);
        const float4 w4 = ((const float4*)rw)[g];
        float o0 = vals[i*4+0] * sc * w4.x;
        float o1 = vals[i*4+1] * sc * w4.y;
        float o2 = vals[i*4+2] * sc * w4.z;
        float o3 = vals[i*4+3] * sc * w4.w;
        uint2 st;
        st.x = h2_as_u32(__floats2half2_rn(o0, o1));
        st.y = h2_as_u32(__floats2half2_rn(o2, o3));
        ((uint2*)(g_yh[dir] + (size_t)row * DINNER))[g] = st;
    }
}

// ===================== residual + LayerNorm (adds split-K partials) =========
__global__ __launch_bounds__(256) void ln_kernel(const float* __restrict__ x,
        const float* __restrict__ pb, const float* __restrict__ lw,
        const float* __restrict__ lb, float* __restrict__ out) {
    int row = blockIdx.x;
    const float* hr  = g_hbuf  + (size_t)row * DMODEL;
    const float* hr2 = g_hbuf2 + (size_t)row * DMODEL;
    const float* xr = x + (size_t)row * DMODEL;
    float v[4];
    float sum = 0.f;
#pragma unroll
    for (int i = 0; i < 4; i++) {
        int c = threadIdx.x + (i << 8);
        v[i] = (hr[c] + hr2[c]) + xr[c] + pb[c];
        sum += v[i];
    }
    __shared__ float red[8];
    __shared__ float s_mu, s_inv;
#pragma unroll
    for (int o = 16; o; o >>= 1) sum += __shfl_xor_sync(0xffffffffu, sum, o);
    if ((threadIdx.x & 31) == 0) red[threadIdx.x >> 5] = sum;
    __syncthreads();
    if (threadIdx.x == 0) {
        float tot = 0.f;
#pragma unroll
        for (int i = 0; i < 8; i++) tot += red[i];
        s_mu = tot / (float)DMODEL;
    }
    __syncthreads();
    float mu = s_mu;
    float vs = 0.f;
#pragma unroll
    for (int i = 0; i < 4; i++) { float d = v[i] - mu; vs = fmaf(d, d, vs); }
#pragma unroll
    for (int o = 16; o; o >>= 1) vs += __shfl_xor_sync(0xffffffffu, vs, o);
    if ((threadIdx.x & 31) == 0) red[threadIdx.x >> 5] = vs;
    __syncthreads();
    if (threadIdx.x == 0) {
        float tot = 0.f;
#pragma unroll
        for (int i = 0; i < 8; i++) tot += red[i];
        s_inv = rsqrtf(tot / (float)DMODEL + 1e-5f);
    }
    __syncthreads();
    float inv = s_inv;
#pragma unroll
    for (int i = 0; i < 4; i++) {
        int c = threadIdx.x + (i << 8);
        out[(size_t)row * DMODEL + c] = (v[i] - mu) * inv * lw[c] + lb[c];
    }
}

// ===================== host orchestration ===================================
extern "C" void kernel_launch(void* const* d_in, const int* in_sizes, int n_in,
                              void* d_out, int out_size) {
    const float* x            = (const float*)d_in[0];
    const float* f_in_proj_w  = (const float*)d_in[1];
    const float* f_conv_w     = (const float*)d_in[2];
    const float* f_conv_b     = (const float*)d_in[3];
    const float* f_dt_bias    = (const float*)d_in[4];
    const float* f_A_log      = (const float*)d_in[5];
    const float* f_D          = (const float*)d_in[6];
    const float* f_rms_w      = (const float*)d_in[7];
    const float* f_out_proj_w = (const float*)d_in[8];
    const float* b_in_proj_w  = (const float*)d_in[9];
    const float* b_conv_w     = (const float*)d_in[10];
    const float* b_conv_b     = (const float*)d_in[11];
    const float* b_dt_bias    = (const float*)d_in[12];
    const float* b_A_log      = (const float*)d_in[13];
    const float* b_D          = (const float*)d_in[14];
    const float* b_rms_w      = (const float*)d_in[15];
    const float* b_out_proj_w = (const float*)d_in[16];
    const float* proj_w       = (const float*)d_in[17];
    const float* proj_b       = (const float*)d_in[18];
    const float* ln_w         = (const float*)d_in[19];
    const float* ln_b         = (const float*)d_in[20];
    float* out = (float*)d_out;

    float *p_hbuf, *p_hbuf2;
    __half *p_zxh, *p_xh, *p_wip, *p_yh, *p_woh, *p_cath, *p_wprh;
    cudaGetSymbolAddress((void**)&p_zxh, g_zxh);
    cudaGetSymbolAddress((void**)&p_hbuf, g_hbuf);
    cudaGetSymbolAddress((void**)&p_hbuf2, g_hbuf2);
    cudaGetSymbolAddress((void**)&p_xh, g_xh);
    cudaGetSymbolAddress((void**)&p_wip, g_wip_h);
    cudaGetSymbolAddress((void**)&p_yh, g_yh);
    cudaGetSymbolAddress((void**)&p_woh, g_woh);
    cudaGetSymbolAddress((void**)&p_cath, g_cath);
    cudaGetSymbolAddress((void**)&p_wprh, g_wprh);

    cudaFuncSetAttribute(gemm_hmma, cudaFuncAttributeMaxDynamicSharedMemorySize, G_SMEM);

    const size_t XSZ  = (size_t)M_ROWS * DMODEL;
    const size_t WIPS = (size_t)DINPROJ_PAD * DMODEL;
    const size_t YSZ  = (size_t)M_ROWS * DINNER;
    const size_t WOS  = (size_t)DMODEL * DINNER;

    // 0) converts: x (1 launch) + all 5 weight tensors (1 launch)
    cvt_x_kernel<<<(int)(XSZ / 8 / 256), 256>>>(x);
    cvt_allw_kernel<<<(W8_TOTAL + 255) / 256, 256>>>(f_in_proj_w, b_in_proj_w,
                                                     f_out_proj_w, b_out_proj_w, proj_w);

    // 1) in_proj GEMMs merged over z, fp16 output (emode 2) -> g_zxh
    {
        dim3 grid(DINPROJ_PAD / 128, M_ROWS / 128, 2);
        gemm_hmma<<<grid, 256, G_SMEM>>>(p_xh, XSZ, p_wip, WIPS,
                                         (float*)p_zxh, (size_t)M_ROWS * DINPROJ,
                                         DMODEL, DMODEL, DMODEL, DINPROJ, DINPROJ, 2);
    }

    // 1b) fp32 dt dot products -> g_dtraw; dt/dA
    fix_dt_kernel<<<2 * M_ROWS, 256>>>(x, f_in_proj_w, b_in_proj_w);
    dt_kernel<<<(2 * M_ROWS * NHEADS + 255) / 256, 256>>>(f_dt_bias, f_A_log, b_dt_bias, b_A_log);

    // 2) conv + silu (fp16 input)
    conv_silu<<<(2 * M_ROWS * (CONVDIM / 4) + 255) / 256, 256>>>(f_conv_w, f_conv_b, b_conv_w, b_conv_b);

    // 3) scan (smem staged)
    scan_kernel<<<128, 256>>>();

    // 4) gate + rmsnorm -> fp16 (z read from fp16 zx)
    gate_rms<<<2 * M_ROWS, 256>>>(f_D, f_rms_w, b_D, b_rms_w);

    // 5) out_proj GEMMs merged over z (BN=128), fused concat
    {
        dim3 grid(DMODEL / 128, M_ROWS / 128, 2);
        gemm_hmma<<<grid, 256, G_SMEM>>>(p_yh, YSZ, p_woh, WOS, (float*)nullptr, 0,
                                         DINNER, DINNER, DINNER, DMODEL, DMODEL, 1);
    }

    // 6) final proj GEMM, split-K=2 over z: K halves -> g_hbuf / g_hbuf2
    {
        dim3 grid(DMODEL / 128, M_ROWS / 128, 2);
        gemm_hmma<<<grid, 256, G_SMEM>>>(p_cath, 1024, p_wprh, 1024,
                                         p_hbuf, (size_t)(p_hbuf2 - p_hbuf),
                                         DMODEL, DINNER, DINNER, DMODEL, DMODEL, 0);
    }

    // 7) residual + LayerNorm (sums split-K partials)
    ln_kernel<<<M_ROWS, 256>>>(x, proj_b, ln_w, ln_b, out);
}